// round 11
// baseline (speedup 1.0000x reference)
#include <cuda_runtime.h>
#include <cuda_bf16.h>
#include <math.h>

#define NB   8
#define NC   128
#define NL   48
#define NT   24
#define NR   8
#define SIG2 1.0001f
#define PICF ((float)(3.14159265358979323846 / 24.0))

#define COV_N      3072
#define COV_ELEMS  9437184ull
#define MEAN_ELEMS 24576

__device__ float g_U[NT * NT];
__device__ float g_s[NT];
__device__ float g_A[NT * NT];
__device__ float g_Wm[NT * NT * 25];
__device__ float g_Bt[NC * NC];
__device__ float g_R[NT * NC * NC];
__device__ float g_G[NT * NC * NC];

// ---------------- LAPACK helper clones (fp32) ----------------
__device__ __forceinline__ float f_lapy2(float x, float y) {
    float ax = fabsf(x), ay = fabsf(y);
    float w = fmaxf(ax, ay), z = fminf(ax, ay);
    if (z == 0.f) return w;
    float q = z / w;
    return w * sqrtf(1.f + q * q);
}

// LAPACK >= 3.10 slartg: c >= 0, r = sign(f)*d, s = g/r
__device__ __forceinline__ void f_lartg(float f, float g, float* c, float* s, float* r) {
    if (g == 0.f)      { *c = 1.f; *s = 0.f; *r = f; }
    else if (f == 0.f) { *c = 0.f; *s = copysignf(1.f, g); *r = fabsf(g); }
    else {
        float d = sqrtf(f * f + g * g);
        *c = fabsf(f) / d;
        *r = copysignf(d, f);
        *s = g / (*r);
    }
}

__device__ void f_laev2(float a, float b, float c,
                        float* rt1, float* rt2, float* cs1, float* sn1) {
    float sm = a + c, df = a - c, adf = fabsf(df), tb = b + b, ab = fabsf(tb);
    float acmx, acmn;
    if (fabsf(a) > fabsf(c)) { acmx = a; acmn = c; } else { acmx = c; acmn = a; }
    float rt;
    if (adf > ab)      { float q = ab / adf; rt = adf * sqrtf(1.f + q * q); }
    else if (adf < ab) { float q = adf / ab; rt = ab * sqrtf(1.f + q * q); }
    else               rt = ab * sqrtf(2.f);
    int sgn1;
    if (sm < 0.f)      { *rt1 = 0.5f * (sm - rt); sgn1 = -1; *rt2 = (acmx / *rt1) * acmn - (b / *rt1) * b; }
    else if (sm > 0.f) { *rt1 = 0.5f * (sm + rt); sgn1 =  1; *rt2 = (acmx / *rt1) * acmn - (b / *rt1) * b; }
    else               { *rt1 = 0.5f * rt; *rt2 = -0.5f * rt; sgn1 = 1; }
    int sgn2; float cs;
    if (df >= 0.f) { cs = df + rt; sgn2 = 1; } else { cs = df - rt; sgn2 = -1; }
    float acs = fabsf(cs);
    if (acs > ab) {
        float ct = -tb / cs;
        *sn1 = 1.f / sqrtf(1.f + ct * ct);
        *cs1 = ct * (*sn1);
    } else {
        if (ab == 0.f) { *cs1 = 1.f; *sn1 = 0.f; }
        else {
            float tn = -cs / tb;
            *cs1 = 1.f / sqrtf(1.f + tn * tn);
            *sn1 = tn * (*cs1);
        }
    }
    if (sgn1 == sgn2) { float tn = *cs1; *cs1 = -(*sn1); *sn1 = tn; }
}

// ---------------- K1: ssyevd-faithful eig of Kc, then A and Wm -------------
// ssytd2(UPLO='L') -> ssteqr('I') -> sort -> sormtr. One warp; scalar control
// replicated on all lanes via private arrays (uniform, no divergence); Z
// rotation updates row-owned, sormtr column-owned.
__global__ void k_eig() {
    __shared__ float As[NT][NT + 1];   // matrix / reflector storage
    __shared__ float Zs[NT][NT + 1];   // eigenvectors
    __shared__ float Aq[NT][NT + 1];   // A = Kfc @ U
    __shared__ float wsh[NT], vsh[NT];
    const int lane = threadIdx.x;      // 32 threads

    float t[2 * NT];
    for (int k = 0; k < 2 * NT; k++) t[k] = (float)k * PICF;

    if (lane < NT) {
        for (int j = 0; j < NT; j++) {
            As[lane][j] = expf(-fabsf(t[lane] - t[j]));
            Zs[lane][j] = (lane == j) ? 1.f : 0.f;
        }
    }
    __syncwarp();

    float d[NT], e[NT], tau[NT];

    // ---- SSYTD2 (lower) ----
    for (int i = 0; i < NT - 1; i++) {
        float alpha = As[i + 1][i];
        float taui = 0.f;
        if (i < NT - 2) {
            float ss = 0.f;
            for (int r = i + 2; r < NT; r++) ss += As[r][i] * As[r][i];
            if (ss != 0.f) {
                float xnorm = sqrtf(ss);
                float beta = -copysignf(f_lapy2(alpha, xnorm), alpha);
                taui = (beta - alpha) / beta;
                float scal = 1.f / (alpha - beta);
                if (lane == 0)
                    for (int r = i + 2; r < NT; r++) As[r][i] *= scal;
                __syncwarp();
                e[i] = beta;
                // x = taui * A_sub * v  (row per lane), v_{i+1}=1, v_r=As[r][i]
                float xr = 0.f, vr = 0.f;
                if (lane >= i + 1 && lane < NT) {
                    vr = (lane == i + 1) ? 1.f : As[lane][i];
                    for (int cc = i + 1; cc < NT; cc++) {
                        float vc = (cc == i + 1) ? 1.f : As[cc][i];
                        xr += As[lane][cc] * vc;
                    }
                    xr *= taui;
                }
                float pv = (lane >= i + 1 && lane < NT) ? vr * xr : 0.f;
                for (int o = 16; o; o >>= 1) pv += __shfl_xor_sync(0xffffffffu, pv, o);
                float a2 = -0.5f * taui * pv;
                float wr = xr + a2 * vr;
                if (lane < NT) { wsh[lane] = wr; vsh[lane] = vr; }
                __syncwarp();
                if (lane >= i + 1 && lane < NT)
                    for (int cc = i + 1; cc < NT; cc++)
                        As[lane][cc] -= vr * wsh[cc] + wr * vsh[cc];
                __syncwarp();
            } else e[i] = alpha;
        } else e[i] = alpha;
        tau[i] = taui;
        d[i] = As[i][i];
    }
    d[NT - 1] = As[NT - 1][NT - 1];

    // ---- SSTEQR('I') ----
    const float eps = 5.9604645e-8f, eps2 = eps * eps, safmin = 1.1754944e-38f;
    int l1 = 0, jtot = 0;
    const int nmaxit = NT * 30;
    while (l1 < NT) {
        if (l1 > 0) e[l1 - 1] = 0.f;
        int m;
        for (m = l1; m < NT - 1; m++) {
            float tst = fabsf(e[m]);
            if (tst == 0.f) break;
            if (tst <= (sqrtf(fabsf(d[m])) * sqrtf(fabsf(d[m + 1]))) * eps) { e[m] = 0.f; break; }
        }
        int l = l1, lsv = l, lend = m, lendsv = lend;
        l1 = m + 1;
        if (lend == l) continue;
        if (fabsf(d[lend]) < fabsf(d[l])) { lend = lsv; l = lendsv; }  // swap

        if (lend > l) {
            // ---- QL ----
            for (;;) {
                if (l != lend) {
                    for (m = l; m < lend; m++) {
                        float tst = e[m] * e[m];
                        if (tst <= (eps2 * fabsf(d[m])) * fabsf(d[m + 1]) + safmin) break;
                    }
                } else m = lend;
                if (m < lend) e[m] = 0.f;
                float p = d[l];
                if (m == l) { d[l] = p; l++; if (l <= lend) continue; else break; }
                if (m == l + 1) {
                    float rt1, rt2, c, s;
                    f_laev2(d[l], e[l], d[l + 1], &rt1, &rt2, &c, &s);
                    if (lane < NT) {
                        float z1 = Zs[lane][l + 1], z0 = Zs[lane][l];
                        Zs[lane][l + 1] = c * z1 - s * z0;
                        Zs[lane][l]     = s * z1 + c * z0;
                    }
                    d[l] = rt1; d[l + 1] = rt2; e[l] = 0.f;
                    l += 2; if (l <= lend) continue; else break;
                }
                if (jtot == nmaxit) break;
                jtot++;
                float g = (d[l + 1] - p) / (2.f * e[l]);
                float r = f_lapy2(g, 1.f);
                g = d[m] - p + e[l] / (g + copysignf(r, g));
                float s = 1.f, c = 1.f;
                p = 0.f;
                for (int i = m - 1; i >= l; i--) {
                    float f = s * e[i], b = c * e[i];
                    f_lartg(g, f, &c, &s, &r);
                    if (i != m - 1) e[i + 1] = r;
                    g = d[i + 1] - p;
                    r = (d[i] - g) * s + 2.f * c * b;
                    p = s * r;
                    d[i + 1] = g + p;
                    g = c * r - b;
                    // stored rotation (c, -s), LASR 'R','V','B' == generation order
                    if (lane < NT) {
                        float z1 = Zs[lane][i + 1], z0 = Zs[lane][i];
                        Zs[lane][i + 1] =  c * z1 + s * z0;
                        Zs[lane][i]     = -s * z1 + c * z0;
                    }
                }
                d[l] -= p;
                e[l] = g;
            }
        } else {
            // ---- QR ----
            for (;;) {
                if (l != lend) {
                    for (m = l; m > lend; m--) {
                        float tst = e[m - 1] * e[m - 1];
                        if (tst <= (eps2 * fabsf(d[m])) * fabsf(d[m - 1]) + safmin) break;
                    }
                } else m = lend;
                if (m > lend) e[m - 1] = 0.f;
                float p = d[l];
                if (m == l) { d[l] = p; l--; if (l >= lend) continue; else break; }
                if (m == l - 1) {
                    float rt1, rt2, c, s;
                    f_laev2(d[l - 1], e[l - 1], d[l], &rt1, &rt2, &c, &s);
                    if (lane < NT) {
                        float z1 = Zs[lane][l], z0 = Zs[lane][l - 1];
                        Zs[lane][l]     = c * z1 - s * z0;
                        Zs[lane][l - 1] = s * z1 + c * z0;
                    }
                    d[l - 1] = rt1; d[l] = rt2; e[l - 1] = 0.f;
                    l -= 2; if (l >= lend) continue; else break;
                }
                if (jtot == nmaxit) break;
                jtot++;
                float g = (d[l - 1] - p) / (2.f * e[l - 1]);
                float r = f_lapy2(g, 1.f);
                g = d[m] - p + e[l - 1] / (g + copysignf(r, g));
                float s = 1.f, c = 1.f;
                p = 0.f;
                for (int i = m; i <= l - 1; i++) {
                    float f = s * e[i], b = c * e[i];
                    f_lartg(g, f, &c, &s, &r);
                    if (i != m) e[i - 1] = r;
                    g = d[i] - p;
                    r = (d[i + 1] - g) * s + 2.f * c * b;
                    p = s * r;
                    d[i] = g + p;
                    g = c * r - b;
                    // stored rotation (c, s), LASR 'R','V','F' == generation order
                    if (lane < NT) {
                        float z1 = Zs[lane][i + 1], z0 = Zs[lane][i];
                        Zs[lane][i + 1] = c * z1 - s * z0;
                        Zs[lane][i]     = s * z1 + c * z0;
                    }
                }
                d[l] -= p;
                e[l - 1] = g;
            }
        }
    }

    // ---- eigen sort ascending (selection sort, LAPACK order) ----
    for (int ii = 1; ii < NT; ii++) {
        int i = ii - 1, k = i;
        float p = d[i];
        for (int j = ii; j < NT; j++) if (d[j] < p) { k = j; p = d[j]; }
        if (k != i) {
            d[k] = d[i]; d[i] = p;
            if (lane < NT) { float tm = Zs[lane][i]; Zs[lane][i] = Zs[lane][k]; Zs[lane][k] = tm; }
        }
    }
    __syncwarp();

    // ---- SORMTR('L','L','N'): Z := H(1)...H(n-1) Z, apply i = n-1..1 ----
    if (lane < NT) {
        int j = lane;
        for (int i = NT - 2; i >= 0; i--) {
            float ti = tau[i];
            if (ti == 0.f) continue;
            float w = Zs[i + 1][j];
            for (int r = i + 2; r < NT; r++) w += As[r][i] * Zs[r][j];
            w *= ti;
            Zs[i + 1][j] -= w;
            for (int r = i + 2; r < NT; r++) Zs[r][j] -= As[r][i] * w;
        }
    }
    __syncwarp();

    if (lane < NT) g_s[lane] = d[lane];
    for (int idx = lane; idx < NT * NT; idx += 32) g_U[idx] = Zs[idx / NT][idx % NT];

    // ---- A = Kfc @ U ----
    for (int idx = lane; idx < NT * NT; idx += 32) {
        int f = idx / NT, l2 = idx % NT;
        float acc = 0.f;
        for (int i2 = 0; i2 < NT; i2++)
            acc += expf(-fabsf(t[NT + f] - t[i2])) * Zs[i2][l2];
        Aq[f][l2] = acc;
        g_A[idx] = acc;
    }
    __syncwarp();

    // ---- Wm[(f,g)] = [-A[f,i]A[g,i] (24), Kff[f,g]] ----
    for (int idx = lane; idx < NT * NT * 25; idx += 32) {
        int fg = idx / 25, i2 = idx % 25;
        int f = fg / NT, g2 = fg % NT;
        g_Wm[idx] = (i2 == 24) ? expf(-fabsf(t[NT + f] - t[NT + g2]))
                               : -Aq[f][i2] * Aq[g2][i2];
    }
}

// ---------------- K0: Bt = V V^T + diag(task_var) ----------------
__global__ void k_bt(const float* __restrict__ V, const float* __restrict__ tv) {
    int idx = blockIdx.x * 256 + threadIdx.x;
    int c = idx >> 7, d = idx & 127;
    float acc = (c == d) ? tv[c] : 0.f;
#pragma unroll
    for (int k = 0; k < NR; k++) acc += V[c * NR + k] * V[d * NR + k];
    g_Bt[idx] = acc;
}

// ---------------- K2: Woodbury -> R_i = Bt (s_i Bt + sig2 I)^{-1} ----------
__global__ void k_wood(const float* __restrict__ Vg, const float* __restrict__ tv) {
    int i = blockIdx.x;
    int tid = threadIdx.x;
    float si = g_s[i];

    __shared__ float dinv[NC];
    __shared__ float Vs[NC][NR];
    __shared__ float E[NC][NR];
    __shared__ float F[NC][NR];
    __shared__ float Ssm[NR][NR];
    __shared__ float Cinv[NR][NR];

    dinv[tid] = 1.f / (si * tv[tid] + SIG2);
#pragma unroll
    for (int k = 0; k < NR; k++) Vs[tid][k] = Vg[tid * NR + k];
    __syncthreads();

    {
        float acc[NR];
#pragma unroll
        for (int k = 0; k < NR; k++) acc[k] = 0.f;
        for (int e = 0; e < NC; e++) {
            float b = g_Bt[tid * NC + e] * dinv[e];
#pragma unroll
            for (int k = 0; k < NR; k++) acc[k] += b * Vs[e][k];
        }
#pragma unroll
        for (int k = 0; k < NR; k++) E[tid][k] = acc[k];
    }
    if (tid < NR * NR) {
        int k = tid >> 3, l = tid & 7;
        float acc = 0.f;
        for (int e = 0; e < NC; e++) acc += Vs[e][k] * Vs[e][l] * dinv[e];
        Ssm[k][l] = ((k == l) ? 1.f : 0.f) + si * acc;
    }
    __syncthreads();
    if (tid == 0) {
        float M[NR][2 * NR];
        for (int r = 0; r < NR; r++)
            for (int c2 = 0; c2 < NR; c2++) {
                M[r][c2] = Ssm[r][c2];
                M[r][NR + c2] = (r == c2) ? 1.f : 0.f;
            }
        for (int p = 0; p < NR; p++) {
            float piv = 1.f / M[p][p];
            for (int c2 = 0; c2 < 2 * NR; c2++) M[p][c2] *= piv;
            for (int r = 0; r < NR; r++) {
                if (r == p) continue;
                float fct = M[r][p];
                for (int c2 = 0; c2 < 2 * NR; c2++) M[r][c2] -= fct * M[p][c2];
            }
        }
        for (int r = 0; r < NR; r++)
            for (int c2 = 0; c2 < NR; c2++) Cinv[r][c2] = M[r][NR + c2];
    }
    __syncthreads();
    {
        float acc[NR];
#pragma unroll
        for (int l = 0; l < NR; l++) acc[l] = 0.f;
#pragma unroll
        for (int k = 0; k < NR; k++) {
            float e = E[tid][k];
#pragma unroll
            for (int l = 0; l < NR; l++) acc[l] += e * Cinv[k][l];
        }
#pragma unroll
        for (int l = 0; l < NR; l++) F[tid][l] = acc[l];
    }
    __syncthreads();
    float fk[NR];
#pragma unroll
    for (int k = 0; k < NR; k++) fk[k] = F[tid][k];
    for (int e = 0; e < NC; e++) {
        float acc = 0.f;
#pragma unroll
        for (int k = 0; k < NR; k++) acc += fk[k] * Vs[e][k];
        g_R[(i * NC + tid) * NC + e] = dinv[e] * (g_Bt[tid * NC + e] - si * acc);
    }
}

// ---------------- K3: G_i = R_i * Bt ---------------------------------------
__global__ void k_G() {
    int i = blockIdx.x;
    int cb = blockIdx.y;
    int tid = threadIdx.x;
    __shared__ float Rs[32][NC];
    for (int idx = tid; idx < 32 * NC; idx += 256)
        Rs[idx / NC][idx % NC] = g_R[(i * NC + cb * 32 + idx / NC) * NC + (idx % NC)];
    __syncthreads();

    int cl = tid >> 3;
    int dg = (tid & 7) * 16;
    float acc[16];
#pragma unroll
    for (int d = 0; d < 16; d++) acc[d] = 0.f;
    for (int e = 0; e < NC; e++) {
        float r = Rs[cl][e];
        const float4* bt = reinterpret_cast<const float4*>(&g_Bt[e * NC + dg]);
#pragma unroll
        for (int v = 0; v < 4; v++) {
            float4 b = bt[v];
            acc[v * 4 + 0] += r * b.x;
            acc[v * 4 + 1] += r * b.y;
            acc[v * 4 + 2] += r * b.z;
            acc[v * 4 + 3] += r * b.w;
        }
    }
    int c = cb * 32 + cl;
    float4* gout = reinterpret_cast<float4*>(&g_G[(i * NC + c) * NC + dg]);
#pragma unroll
    for (int v = 0; v < 4; v++)
        gout[v] = make_float4(acc[v * 4 + 0], acc[v * 4 + 1], acc[v * 4 + 2], acc[v * 4 + 3]);
}

// ---------------- K4: mean --------------------------------------------------
// Quirks: T = U @ Y (reference einsum, no transpose); loc via element-wise
// jnp.repeat: Y[j][c] = x[c][24+j] - 0.5*(x[c][12+j/2] + x[c][36+j/2]).
__global__ void k_mean(const float* __restrict__ x, float* __restrict__ out) {
    int b = blockIdx.x, tid = threadIdx.x;
    __shared__ float Ys[NT][NC];
    __shared__ float Ts[NT][NC];
    __shared__ float Q[NT][NC];
    __shared__ float Us[NT][NT];

    for (int idx = tid; idx < NT * NT; idx += 128) Us[idx / NT][idx % NT] = g_U[idx];

    const float* xr = x + (size_t)(b * NC + tid) * NL;
    float xv[NL];
#pragma unroll
    for (int l = 0; l < NL; l++) xv[l] = xr[l];
#pragma unroll
    for (int j = 0; j < NT; j++) {
        int h = j >> 1;
        Ys[j][tid] = xv[NT + j] - 0.5f * (xv[12 + h] + xv[36 + h]);
    }
    __syncthreads();

#pragma unroll 1
    for (int i = 0; i < NT; i++) {
        float acc = 0.f;
#pragma unroll
        for (int j = 0; j < NT; j++) acc += Us[i][j] * Ys[j][tid];
        Ts[i][tid] = acc;
    }
    __syncthreads();

#pragma unroll 1
    for (int i = 0; i < NT; i++) {
        float acc = 0.f;
        const float* rrow = &g_R[(i * NC + tid) * NC];
        for (int c = 0; c < NC; c++) acc += rrow[c] * Ts[i][c];
        Q[i][tid] = acc;
    }
    __syncthreads();

#pragma unroll 1
    for (int f = 0; f < NT; f++) {
        float acc = 0.f;
#pragma unroll
        for (int i = 0; i < NT; i++) acc += g_A[f * NT + i] * Q[i][tid];
        acc += 0.5f * (xv[f] + xv[NT + f]);
        out[(size_t)(b * NT + f) * NC + tid] = acc;
    }
}

// ---------------- K5: covariance, broadcast 8 batches -----------------------
__global__ void __launch_bounds__(256, 1) k_cov(float* __restrict__ out) {
    float* cov = out + MEAN_ELEMS;
    int patch = blockIdx.x;
    int fgBase = blockIdx.y * 16;
    int tid = threadIdx.x;

    __shared__ float Wsm[16 * 25];
    for (int idx = tid; idx < 16 * 25; idx += 256) Wsm[idx] = g_Wm[fgBase * 25 + idx];

    int c  = (patch >> 2) * 32 + (tid >> 3);
    int d0 = (patch & 3) * 32 + (tid & 7) * 4;

    float4 bt = *reinterpret_cast<const float4*>(&g_Bt[c * NC + d0]);
    float4 gg[NT];
#pragma unroll
    for (int i = 0; i < NT; i++)
        gg[i] = *reinterpret_cast<const float4*>(&g_G[(i * NC + c) * NC + d0]);
    __syncthreads();

#pragma unroll 1
    for (int t = 0; t < 16; t++) {
        int fg = fgBase + t;
        int f = fg / NT, g = fg % NT;
        const float* w = &Wsm[t * 25];
        float w24 = w[24];
        float4 acc;
        acc.x = w24 * bt.x; acc.y = w24 * bt.y; acc.z = w24 * bt.z; acc.w = w24 * bt.w;
#pragma unroll
        for (int i = 0; i < NT; i++) {
            float wi = w[i];
            acc.x += wi * gg[i].x;
            acc.y += wi * gg[i].y;
            acc.z += wi * gg[i].z;
            acc.w += wi * gg[i].w;
        }
        if (f == g && c >= d0 && c < d0 + 4)
            reinterpret_cast<float*>(&acc)[c - d0] += SIG2;
        size_t row = (size_t)(f * NC + c);
        size_t col = (size_t)(g * NC + d0);
        float* p = cov + row * COV_N + col;
#pragma unroll
        for (int b = 0; b < NB; b++) {
            __stcs(reinterpret_cast<float4*>(p), acc);
            p += COV_ELEMS;
        }
    }
}

// ---------------- launcher ---------------------------------------------------
extern "C" void kernel_launch(void* const* d_in, const int* in_sizes, int n_in,
                              void* d_out, int out_size) {
    const float* x  = (const float*)d_in[0];
    const float* V  = (const float*)d_in[1];
    const float* tv = (const float*)d_in[2];
    float* out = (float*)d_out;

    k_bt<<<64, 256>>>(V, tv);
    k_eig<<<1, 32>>>();
    k_wood<<<24, 128>>>(V, tv);
    k_G<<<dim3(24, 4), 256>>>();
    k_mean<<<8, 128>>>(x, out);
    k_cov<<<dim3(16, 36), 256>>>(out);
}

// round 12
// speedup vs baseline: 1.6132x; 1.6132x over previous
#include <cuda_runtime.h>
#include <cuda_bf16.h>
#include <math.h>

#define NB   8
#define NC   128
#define NL   48
#define NT   24
#define NR   8
#define SIG2 1.0001f
#define PICF ((float)(3.14159265358979323846 / 24.0))

#define COV_N      3072
#define COV_ELEMS  9437184ull
#define MEAN_ELEMS 24576

__device__ float g_U[NT * NT];
__device__ float g_s[NT];
__device__ float g_A[NT * NT];
__device__ float g_Wm[NT * NT * 25];
__device__ float g_Bt[NC * NC];
__device__ float g_W[NT * NC * NR];     // W_i = D_i^-1 V          (96 KB)
__device__ float g_Z[NT * NC * NR];     // Z_i = W_i S_i^-1        (96 KB)
__device__ float g_gamma[NT * NC];      // diag term of G_i
__device__ float g_G[NT * NC * NC];     // G_i (consumed by k_cov)

// ---------------- LAPACK helper clones (fp32) ----------------
__device__ __forceinline__ float f_lapy2(float x, float y) {
    float ax = fabsf(x), ay = fabsf(y);
    float w = fmaxf(ax, ay), z = fminf(ax, ay);
    if (z == 0.f) return w;
    float q = z / w;
    return w * sqrtf(1.f + q * q);
}

// LAPACK >= 3.10 slartg: c >= 0, r = sign(f)*d, s = g/r
__device__ __forceinline__ void f_lartg(float f, float g, float* c, float* s, float* r) {
    if (g == 0.f)      { *c = 1.f; *s = 0.f; *r = f; }
    else if (f == 0.f) { *c = 0.f; *s = copysignf(1.f, g); *r = fabsf(g); }
    else {
        float d = sqrtf(f * f + g * g);
        *c = fabsf(f) / d;
        *r = copysignf(d, f);
        *s = g / (*r);
    }
}

__device__ void f_laev2(float a, float b, float c,
                        float* rt1, float* rt2, float* cs1, float* sn1) {
    float sm = a + c, df = a - c, adf = fabsf(df), tb = b + b, ab = fabsf(tb);
    float acmx, acmn;
    if (fabsf(a) > fabsf(c)) { acmx = a; acmn = c; } else { acmx = c; acmn = a; }
    float rt;
    if (adf > ab)      { float q = ab / adf; rt = adf * sqrtf(1.f + q * q); }
    else if (adf < ab) { float q = adf / ab; rt = ab * sqrtf(1.f + q * q); }
    else               rt = ab * sqrtf(2.f);
    int sgn1;
    if (sm < 0.f)      { *rt1 = 0.5f * (sm - rt); sgn1 = -1; *rt2 = (acmx / *rt1) * acmn - (b / *rt1) * b; }
    else if (sm > 0.f) { *rt1 = 0.5f * (sm + rt); sgn1 =  1; *rt2 = (acmx / *rt1) * acmn - (b / *rt1) * b; }
    else               { *rt1 = 0.5f * rt; *rt2 = -0.5f * rt; sgn1 = 1; }
    int sgn2; float cs;
    if (df >= 0.f) { cs = df + rt; sgn2 = 1; } else { cs = df - rt; sgn2 = -1; }
    float acs = fabsf(cs);
    if (acs > ab) {
        float ct = -tb / cs;
        *sn1 = 1.f / sqrtf(1.f + ct * ct);
        *cs1 = ct * (*sn1);
    } else {
        if (ab == 0.f) { *cs1 = 1.f; *sn1 = 0.f; }
        else {
            float tn = -cs / tb;
            *cs1 = 1.f / sqrtf(1.f + tn * tn);
            *sn1 = tn * (*cs1);
        }
    }
    if (sgn1 == sgn2) { float tn = *cs1; *cs1 = -(*sn1); *sn1 = tn; }
}

// ---------------- K1: ssyevd-faithful eig of Kc, then A and Wm -------------
// Identical fp32 arithmetic to the R11 passing version; state arrays moved
// from local memory to lane-private shared rows (bit-identical results,
// much shorter serial chains), d-recurrence register-carried.
__global__ void k_eig() {
    __shared__ float As[NT][NT + 1];
    __shared__ float Zs[NT][NT + 1];
    __shared__ float Aq[NT][NT + 1];
    __shared__ float wsh[NT], vsh[NT];
    __shared__ float ds[32][NT + 1];
    __shared__ float es[32][NT + 1];
    __shared__ float taus[32][NT + 1];
    const int lane = threadIdx.x;      // 32 threads

#define D_(ii)   ds[lane][ii]
#define E_(ii)   es[lane][ii]
#define TAU_(ii) taus[lane][ii]

    if (lane < NT) {
        float tl = (float)lane * PICF;
        for (int j = 0; j < NT; j++) {
            As[lane][j] = expf(-fabsf(tl - (float)j * PICF));
            Zs[lane][j] = (lane == j) ? 1.f : 0.f;
        }
    }
    __syncwarp();

    // ---- SSYTD2 (lower) ----
    for (int i = 0; i < NT - 1; i++) {
        float alpha = As[i + 1][i];
        float taui = 0.f;
        if (i < NT - 2) {
            float ss = 0.f;
            for (int r = i + 2; r < NT; r++) ss += As[r][i] * As[r][i];
            if (ss != 0.f) {
                float xnorm = sqrtf(ss);
                float beta = -copysignf(f_lapy2(alpha, xnorm), alpha);
                taui = (beta - alpha) / beta;
                float scal = 1.f / (alpha - beta);
                if (lane == 0)
                    for (int r = i + 2; r < NT; r++) As[r][i] *= scal;
                __syncwarp();
                E_(i) = beta;
                float xr = 0.f, vr = 0.f;
                if (lane >= i + 1 && lane < NT) {
                    vr = (lane == i + 1) ? 1.f : As[lane][i];
                    for (int cc = i + 1; cc < NT; cc++) {
                        float vc = (cc == i + 1) ? 1.f : As[cc][i];
                        xr += As[lane][cc] * vc;
                    }
                    xr *= taui;
                }
                float pv = (lane >= i + 1 && lane < NT) ? vr * xr : 0.f;
                for (int o = 16; o; o >>= 1) pv += __shfl_xor_sync(0xffffffffu, pv, o);
                float a2 = -0.5f * taui * pv;
                float wr = xr + a2 * vr;
                if (lane < NT) { wsh[lane] = wr; vsh[lane] = vr; }
                __syncwarp();
                if (lane >= i + 1 && lane < NT)
                    for (int cc = i + 1; cc < NT; cc++)
                        As[lane][cc] -= vr * wsh[cc] + wr * vsh[cc];
                __syncwarp();
            } else E_(i) = alpha;
        } else E_(i) = alpha;
        TAU_(i) = taui;
        D_(i) = As[i][i];
    }
    D_(NT - 1) = As[NT - 1][NT - 1];

    // ---- SSTEQR('I') ----
    const float eps = 5.9604645e-8f, eps2 = eps * eps, safmin = 1.1754944e-38f;
    int l1 = 0, jtot = 0;
    const int nmaxit = NT * 30;
    while (l1 < NT) {
        if (l1 > 0) E_(l1 - 1) = 0.f;
        int m;
        for (m = l1; m < NT - 1; m++) {
            float tst = fabsf(E_(m));
            if (tst == 0.f) break;
            if (tst <= (sqrtf(fabsf(D_(m))) * sqrtf(fabsf(D_(m + 1)))) * eps) { E_(m) = 0.f; break; }
        }
        int l = l1, lsv = l, lend = m, lendsv = lend;
        l1 = m + 1;
        if (lend == l) continue;
        if (fabsf(D_(lend)) < fabsf(D_(l))) { lend = lsv; l = lendsv; }

        if (lend > l) {
            // ---- QL ----
            for (;;) {
                if (l != lend) {
                    for (m = l; m < lend; m++) {
                        float tst = E_(m) * E_(m);
                        if (tst <= (eps2 * fabsf(D_(m))) * fabsf(D_(m + 1)) + safmin) break;
                    }
                } else m = lend;
                if (m < lend) E_(m) = 0.f;
                float p = D_(l);
                if (m == l) { D_(l) = p; l++; if (l <= lend) continue; else break; }
                if (m == l + 1) {
                    float rt1, rt2, c, s;
                    f_laev2(D_(l), E_(l), D_(l + 1), &rt1, &rt2, &c, &s);
                    if (lane < NT) {
                        float z1 = Zs[lane][l + 1], z0 = Zs[lane][l];
                        Zs[lane][l + 1] = c * z1 - s * z0;
                        Zs[lane][l]     = s * z1 + c * z0;
                    }
                    D_(l) = rt1; D_(l + 1) = rt2; E_(l) = 0.f;
                    l += 2; if (l <= lend) continue; else break;
                }
                if (jtot == nmaxit) break;
                jtot++;
                float g = (D_(l + 1) - p) / (2.f * E_(l));
                float r = f_lapy2(g, 1.f);
                g = D_(m) - p + E_(l) / (g + copysignf(r, g));
                float s = 1.f, c = 1.f;
                p = 0.f;
                float dn = D_(m);
                for (int i = m - 1; i >= l; i--) {
                    float ei = E_(i);
                    float f = s * ei, b = c * ei;
                    f_lartg(g, f, &c, &s, &r);
                    if (i != m - 1) E_(i + 1) = r;
                    g = dn - p;
                    float di = D_(i);
                    r = (di - g) * s + 2.f * c * b;
                    p = s * r;
                    D_(i + 1) = g + p;
                    g = c * r - b;
                    dn = di;
                    if (lane < NT) {
                        float z1 = Zs[lane][i + 1], z0 = Zs[lane][i];
                        Zs[lane][i + 1] =  c * z1 + s * z0;
                        Zs[lane][i]     = -s * z1 + c * z0;
                    }
                }
                D_(l) = dn - p;
                E_(l) = g;
            }
        } else {
            // ---- QR ----
            for (;;) {
                if (l != lend) {
                    for (m = l; m > lend; m--) {
                        float tst = E_(m - 1) * E_(m - 1);
                        if (tst <= (eps2 * fabsf(D_(m))) * fabsf(D_(m - 1)) + safmin) break;
                    }
                } else m = lend;
                if (m > lend) E_(m - 1) = 0.f;
                float p = D_(l);
                if (m == l) { D_(l) = p; l--; if (l >= lend) continue; else break; }
                if (m == l - 1) {
                    float rt1, rt2, c, s;
                    f_laev2(D_(l - 1), E_(l - 1), D_(l), &rt1, &rt2, &c, &s);
                    if (lane < NT) {
                        float z1 = Zs[lane][l], z0 = Zs[lane][l - 1];
                        Zs[lane][l]     = c * z1 - s * z0;
                        Zs[lane][l - 1] = s * z1 + c * z0;
                    }
                    D_(l - 1) = rt1; D_(l) = rt2; E_(l - 1) = 0.f;
                    l -= 2; if (l >= lend) continue; else break;
                }
                if (jtot == nmaxit) break;
                jtot++;
                float g = (D_(l - 1) - p) / (2.f * E_(l - 1));
                float r = f_lapy2(g, 1.f);
                g = D_(m) - p + E_(l - 1) / (g + copysignf(r, g));
                float s = 1.f, c = 1.f;
                p = 0.f;
                float dc = D_(m);
                for (int i = m; i <= l - 1; i++) {
                    float ei = E_(i);
                    float f = s * ei, b = c * ei;
                    f_lartg(g, f, &c, &s, &r);
                    if (i != m) E_(i - 1) = r;
                    g = dc - p;
                    float dip = D_(i + 1);
                    r = (dip - g) * s + 2.f * c * b;
                    p = s * r;
                    D_(i) = g + p;
                    g = c * r - b;
                    dc = dip;
                    if (lane < NT) {
                        float z1 = Zs[lane][i + 1], z0 = Zs[lane][i];
                        Zs[lane][i + 1] = c * z1 - s * z0;
                        Zs[lane][i]     = s * z1 + c * z0;
                    }
                }
                D_(l) = dc - p;
                E_(l - 1) = g;
            }
        }
    }

    // ---- eigen sort ascending (selection sort, LAPACK order) ----
    for (int ii = 1; ii < NT; ii++) {
        int i = ii - 1, k = i;
        float p = D_(i);
        for (int j = ii; j < NT; j++) if (D_(j) < p) { k = j; p = D_(j); }
        if (k != i) {
            D_(k) = D_(i); D_(i) = p;
            if (lane < NT) { float tm = Zs[lane][i]; Zs[lane][i] = Zs[lane][k]; Zs[lane][k] = tm; }
        }
    }
    __syncwarp();

    // ---- SORMTR('L','L','N') ----
    if (lane < NT) {
        int j = lane;
        for (int i = NT - 2; i >= 0; i--) {
            float ti = TAU_(i);
            if (ti == 0.f) continue;
            float w = Zs[i + 1][j];
            for (int r = i + 2; r < NT; r++) w += As[r][i] * Zs[r][j];
            w *= ti;
            Zs[i + 1][j] -= w;
            for (int r = i + 2; r < NT; r++) Zs[r][j] -= As[r][i] * w;
        }
    }
    __syncwarp();

    if (lane < NT) g_s[lane] = D_(lane);
    for (int idx = lane; idx < NT * NT; idx += 32) g_U[idx] = Zs[idx / NT][idx % NT];

    // ---- A = Kfc @ U ----
    for (int idx = lane; idx < NT * NT; idx += 32) {
        int f = idx / NT, l2 = idx % NT;
        float tf = (float)(NT + f) * PICF;
        float acc = 0.f;
        for (int i2 = 0; i2 < NT; i2++)
            acc += expf(-fabsf(tf - (float)i2 * PICF)) * Zs[i2][l2];
        Aq[f][l2] = acc;
        g_A[idx] = acc;
    }
    __syncwarp();

    // ---- Wm ----
    for (int idx = lane; idx < NT * NT * 25; idx += 32) {
        int fg = idx / 25, i2 = idx % 25;
        int f = fg / NT, g2 = fg % NT;
        g_Wm[idx] = (i2 == 24) ? expf(-fabsf((float)(NT + f) * PICF - (float)(NT + g2) * PICF))
                               : -Aq[f][i2] * Aq[g2][i2];
    }
#undef D_
#undef E_
#undef TAU_
}

// ---------------- K0: Bt = V V^T + diag(task_var) ----------------
__global__ void k_bt(const float* __restrict__ V, const float* __restrict__ tv) {
    int idx = blockIdx.x * 256 + threadIdx.x;
    int c = idx >> 7, d = idx & 127;
    float acc = (c == d) ? tv[c] : 0.f;
#pragma unroll
    for (int k = 0; k < NR; k++) acc += V[c * NR + k] * V[d * NR + k];
    g_Bt[idx] = acc;
}

// ---------------- K2: low-rank factors per i -------------------------------
// eps_i = SIG2/s_i, D_i = diag(tv)+eps_i, W_i = D_i^-1 V,
// S_i = I + V^T W_i (8x8), Z_i = W_i S_i^-1,
// gamma_i[c] = (-eps + eps^2/D[c]) / s_i.
__global__ void k_wood(const float* __restrict__ Vg, const float* __restrict__ tv) {
    int i = blockIdx.x;       // 24 blocks
    int c = threadIdx.x;      // 128 threads
    __shared__ float Vs[NC][NR];
    __shared__ float Wsh[NC][NR];
    __shared__ float Ssm[NR][NR];
    __shared__ float Sinv[NR][NR];

    float si  = g_s[i];
    float eps = SIG2 / si;
    float dinv = 1.f / (tv[c] + eps);

    float w[NR];
#pragma unroll
    for (int k = 0; k < NR; k++) {
        float v = Vg[c * NR + k];
        Vs[c][k] = v;
        w[k] = v * dinv;
        Wsh[c][k] = w[k];
    }
    __syncthreads();

    if (c < NR * NR) {
        int k = c >> 3, l = c & 7;
        float acc = 0.f;
        for (int e = 0; e < NC; e++) acc += Vs[e][k] * Wsh[e][l];
        Ssm[k][l] = ((k == l) ? 1.f : 0.f) + acc;
    }
    __syncthreads();
    if (c == 0) {
        float M[NR][2 * NR];
        for (int r = 0; r < NR; r++)
            for (int c2 = 0; c2 < NR; c2++) {
                M[r][c2] = Ssm[r][c2];
                M[r][NR + c2] = (r == c2) ? 1.f : 0.f;
            }
        for (int p = 0; p < NR; p++) {
            float piv = 1.f / M[p][p];
            for (int c2 = 0; c2 < 2 * NR; c2++) M[p][c2] *= piv;
            for (int r = 0; r < NR; r++) {
                if (r == p) continue;
                float fct = M[r][p];
                for (int c2 = 0; c2 < 2 * NR; c2++) M[r][c2] -= fct * M[p][c2];
            }
        }
        for (int r = 0; r < NR; r++)
            for (int c2 = 0; c2 < NR; c2++) Sinv[r][c2] = M[r][NR + c2];
    }
    __syncthreads();

    float z[NR];
#pragma unroll
    for (int k = 0; k < NR; k++) {
        float acc = 0.f;
#pragma unroll
        for (int l = 0; l < NR; l++) acc += w[l] * Sinv[l][k];
        z[k] = acc;
    }
    int base = i * NC * NR + c * NR;
#pragma unroll
    for (int k = 0; k < NR; k++) { g_W[base + k] = w[k]; g_Z[base + k] = z[k]; }
    g_gamma[i * NC + c] = (-eps + eps * eps * dinv) / si;
}

// ---------------- K3: G_i = alpha*Bt + gamma*I - beta * Z W^T ---------------
__global__ void k_G() {
    int i = blockIdx.x;
    int cb = blockIdx.y;
    int tid = threadIdx.x;  // 256
    __shared__ float Wsh[NC][NR + 1];
    __shared__ float gam[NC];
    for (int idx = tid; idx < NC * NR; idx += 256)
        Wsh[idx >> 3][idx & 7] = g_W[i * NC * NR + idx];
    for (int idx = tid; idx < NC; idx += 256) gam[idx] = g_gamma[i * NC + idx];
    __syncthreads();

    float si = g_s[i];
    float eps = SIG2 / si;
    float alpha = 1.f / si;
    float beta = eps * eps / si;

    int c  = cb * 32 + (tid >> 3);
    int dg = (tid & 7) * 16;
    float z[NR];
#pragma unroll
    for (int k = 0; k < NR; k++) z[k] = g_Z[i * NC * NR + c * NR + k];

    const float4* btp = reinterpret_cast<const float4*>(&g_Bt[c * NC + dg]);
    float4* gout = reinterpret_cast<float4*>(&g_G[(i * NC + c) * NC + dg]);
#pragma unroll
    for (int v = 0; v < 4; v++) {
        float4 b = btp[v];
        float o[4];
#pragma unroll
        for (int e = 0; e < 4; e++) {
            int d = dg + v * 4 + e;
            float dot = 0.f;
#pragma unroll
            for (int k = 0; k < NR; k++) dot += z[k] * Wsh[d][k];
            float val = alpha * ((const float*)&b)[e] - beta * dot;
            if (d == c) val += gam[c];
            o[e] = val;
        }
        gout[v] = make_float4(o[0], o[1], o[2], o[3]);
    }
}

// ---------------- K4: mean (low-rank R) -------------------------------------
// Quirks preserved: T = U @ Y; element-wise jnp.repeat loc.
// Q[i][d] = (1/s)T[d] - (e/s)T[d]/D[d] + (e/s)*sum_k Z[d,k]*h[k],
// h[k] = sum_c W[c,k] T[c].
__global__ void k_mean(const float* __restrict__ x, const float* __restrict__ tv,
                       float* __restrict__ out) {
    int b = blockIdx.x, tid = threadIdx.x;  // 128
    __shared__ float Ys[NT][NC];
    __shared__ float Ts[NT][NC];
    __shared__ float Q[NT][NC];
    __shared__ float Us[NT][NT];
    __shared__ float hsh[NR];

    for (int idx = tid; idx < NT * NT; idx += 128) Us[idx / NT][idx % NT] = g_U[idx];
    float tvd = tv[tid];

    const float* xr = x + (size_t)(b * NC + tid) * NL;
    float xv[NL];
#pragma unroll
    for (int l = 0; l < NL; l++) xv[l] = xr[l];
#pragma unroll
    for (int j = 0; j < NT; j++) {
        int h = j >> 1;
        Ys[j][tid] = xv[NT + j] - 0.5f * (xv[12 + h] + xv[36 + h]);
    }
    __syncthreads();

#pragma unroll 1
    for (int i = 0; i < NT; i++) {
        float acc = 0.f;
#pragma unroll
        for (int j = 0; j < NT; j++) acc += Us[i][j] * Ys[j][tid];
        Ts[i][tid] = acc;
    }
    __syncthreads();

    int kk = tid >> 4, j0 = tid & 15;
#pragma unroll 1
    for (int i = 0; i < NT; i++) {
        float si = g_s[i];
        float eps = SIG2 / si;
        float a1 = 1.f / si;
        float q3 = eps / si;
        // h[k] reduction
        float part = 0.f;
#pragma unroll
        for (int t = 0; t < 8; t++) {
            int cc = j0 + 16 * t;
            part += g_W[i * NC * NR + cc * NR + kk] * Ts[i][cc];
        }
#pragma unroll
        for (int off = 8; off; off >>= 1)
            part += __shfl_down_sync(0xffffffffu, part, off, 16);
        if (j0 == 0) hsh[kk] = part;
        __syncthreads();

        float T = Ts[i][tid];
        float dinv = 1.f / (tvd + eps);
        float zh = 0.f;
#pragma unroll
        for (int k2 = 0; k2 < NR; k2++)
            zh += g_Z[i * NC * NR + tid * NR + k2] * hsh[k2];
        Q[i][tid] = a1 * T - q3 * T * dinv + q3 * zh;
        __syncthreads();
    }

#pragma unroll 1
    for (int f = 0; f < NT; f++) {
        float acc = 0.f;
#pragma unroll
        for (int i = 0; i < NT; i++) acc += g_A[f * NT + i] * Q[i][tid];
        acc += 0.5f * (xv[f] + xv[NT + f]);
        out[(size_t)(b * NT + f) * NC + tid] = acc;
    }
}

// ---------------- K5: covariance, broadcast 8 batches (unchanged) -----------
__global__ void __launch_bounds__(256, 1) k_cov(float* __restrict__ out) {
    float* cov = out + MEAN_ELEMS;
    int patch = blockIdx.x;
    int fgBase = blockIdx.y * 16;
    int tid = threadIdx.x;

    __shared__ float Wsm[16 * 25];
    for (int idx = tid; idx < 16 * 25; idx += 256) Wsm[idx] = g_Wm[fgBase * 25 + idx];

    int c  = (patch >> 2) * 32 + (tid >> 3);
    int d0 = (patch & 3) * 32 + (tid & 7) * 4;

    float4 bt = *reinterpret_cast<const float4*>(&g_Bt[c * NC + d0]);
    float4 gg[NT];
#pragma unroll
    for (int i = 0; i < NT; i++)
        gg[i] = *reinterpret_cast<const float4*>(&g_G[(i * NC + c) * NC + d0]);
    __syncthreads();

#pragma unroll 1
    for (int t = 0; t < 16; t++) {
        int fg = fgBase + t;
        int f = fg / NT, g = fg % NT;
        const float* w = &Wsm[t * 25];
        float w24 = w[24];
        float4 acc;
        acc.x = w24 * bt.x; acc.y = w24 * bt.y; acc.z = w24 * bt.z; acc.w = w24 * bt.w;
#pragma unroll
        for (int i = 0; i < NT; i++) {
            float wi = w[i];
            acc.x += wi * gg[i].x;
            acc.y += wi * gg[i].y;
            acc.z += wi * gg[i].z;
            acc.w += wi * gg[i].w;
        }
        if (f == g && c >= d0 && c < d0 + 4)
            reinterpret_cast<float*>(&acc)[c - d0] += SIG2;
        size_t row = (size_t)(f * NC + c);
        size_t col = (size_t)(g * NC + d0);
        float* p = cov + row * COV_N + col;
#pragma unroll
        for (int b = 0; b < NB; b++) {
            __stcs(reinterpret_cast<float4*>(p), acc);
            p += COV_ELEMS;
        }
    }
}

// ---------------- launcher ---------------------------------------------------
extern "C" void kernel_launch(void* const* d_in, const int* in_sizes, int n_in,
                              void* d_out, int out_size) {
    const float* x  = (const float*)d_in[0];
    const float* V  = (const float*)d_in[1];
    const float* tv = (const float*)d_in[2];
    float* out = (float*)d_out;

    k_bt<<<64, 256>>>(V, tv);
    k_eig<<<1, 32>>>();
    k_wood<<<24, 128>>>(V, tv);
    k_G<<<dim3(24, 4), 256>>>();
    k_mean<<<8, 128>>>(x, tv, out);
    k_cov<<<dim3(16, 36), 256>>>(out);
}

// round 13
// speedup vs baseline: 1.8608x; 1.1535x over previous
#include <cuda_runtime.h>
#include <cuda_bf16.h>
#include <math.h>

#define NB   8
#define NC   128
#define NL   48
#define NT   24
#define NR   8
#define SIG2 1.0001f
#define PICF ((float)(3.14159265358979323846 / 24.0))

#define COV_N      3072
#define COV_ELEMS  9437184ull
#define MEAN_ELEMS 24576

__device__ float g_U[NT * NT];
__device__ float g_s[NT];
__device__ float g_A[NT * NT];
__device__ float g_Wm[NT * NT * 25];
__device__ float g_Bt[NC * NC];
__device__ float g_W[NT * NC * NR];     // W_i = D_i^-1 V
__device__ float g_Z[NT * NC * NR];     // Z_i = W_i S_i^-1
__device__ float g_gamma[NT * NC];      // diag term of G_i
__device__ float g_G[NT * NC * NC];     // G_i (consumed by k_cov)

// ---------------- LAPACK helper clones (fp32) ----------------
__device__ __forceinline__ float f_lapy2(float x, float y) {
    float ax = fabsf(x), ay = fabsf(y);
    float w = fmaxf(ax, ay), z = fminf(ax, ay);
    if (z == 0.f) return w;
    float q = z / w;
    return w * sqrtf(1.f + q * q);
}

// Hot-path slartg (LAPACK >= 3.10 convention: c >= 0, r = sign(f)*d, s = g/r),
// rsqrt-based: algebraically identical, no divides/sqrt on the serial chain.
// Values here are O(1); no overflow/underflow guard needed.
__device__ __forceinline__ void f_lartg(float f, float g, float* c, float* s, float* r) {
    if (g == 0.f)      { *c = 1.f; *s = 0.f; *r = f; }
    else if (f == 0.f) { *c = 0.f; *s = copysignf(1.f, g); *r = fabsf(g); }
    else {
        float t2 = f * f + g * g;
        float p  = rsqrtf(t2);
        float d  = t2 * p;
        *c = fabsf(f) * p;
        float sp = g * p;
        *s = (f >= 0.f) ? sp : -sp;
        *r = copysignf(d, f);
    }
}

__device__ void f_laev2(float a, float b, float c,
                        float* rt1, float* rt2, float* cs1, float* sn1) {
    float sm = a + c, df = a - c, adf = fabsf(df), tb = b + b, ab = fabsf(tb);
    float acmx, acmn;
    if (fabsf(a) > fabsf(c)) { acmx = a; acmn = c; } else { acmx = c; acmn = a; }
    float rt;
    if (adf > ab)      { float q = ab / adf; rt = adf * sqrtf(1.f + q * q); }
    else if (adf < ab) { float q = adf / ab; rt = ab * sqrtf(1.f + q * q); }
    else               rt = ab * sqrtf(2.f);
    int sgn1;
    if (sm < 0.f)      { *rt1 = 0.5f * (sm - rt); sgn1 = -1; *rt2 = (acmx / *rt1) * acmn - (b / *rt1) * b; }
    else if (sm > 0.f) { *rt1 = 0.5f * (sm + rt); sgn1 =  1; *rt2 = (acmx / *rt1) * acmn - (b / *rt1) * b; }
    else               { *rt1 = 0.5f * rt; *rt2 = -0.5f * rt; sgn1 = 1; }
    int sgn2; float cs;
    if (df >= 0.f) { cs = df + rt; sgn2 = 1; } else { cs = df - rt; sgn2 = -1; }
    float acs = fabsf(cs);
    if (acs > ab) {
        float ct = -tb / cs;
        *sn1 = 1.f / sqrtf(1.f + ct * ct);
        *cs1 = ct * (*sn1);
    } else {
        if (ab == 0.f) { *cs1 = 1.f; *sn1 = 0.f; }
        else {
            float tn = -cs / tb;
            *cs1 = 1.f / sqrtf(1.f + tn * tn);
            *sn1 = tn * (*cs1);
        }
    }
    if (sgn1 == sgn2) { float tn = *cs1; *cs1 = -(*sn1); *sn1 = tn; }
}

// ---------------- K1: ssyevd-faithful eig of Kc, then A and Wm -------------
__global__ void k_eig() {
    __shared__ float As[NT][NT + 1];
    __shared__ float Zs[NT][NT + 1];
    __shared__ float Aq[NT][NT + 1];
    __shared__ float wsh[NT], vsh[NT];
    __shared__ float ds[32][NT + 1];
    __shared__ float es[32][NT + 1];
    __shared__ float taus[32][NT + 1];
    const int lane = threadIdx.x;      // 32 threads

#define D_(ii)   ds[lane][ii]
#define E_(ii)   es[lane][ii]
#define TAU_(ii) taus[lane][ii]

    if (lane < NT) {
        float tl = (float)lane * PICF;
        for (int j = 0; j < NT; j++) {
            As[lane][j] = expf(-fabsf(tl - (float)j * PICF));
            Zs[lane][j] = (lane == j) ? 1.f : 0.f;
        }
    }
    __syncwarp();

    // ---- SSYTD2 (lower) ----
    for (int i = 0; i < NT - 1; i++) {
        float alpha = As[i + 1][i];
        float taui = 0.f;
        if (i < NT - 2) {
            float ss = 0.f;
            for (int r = i + 2; r < NT; r++) ss += As[r][i] * As[r][i];
            if (ss != 0.f) {
                float xnorm = sqrtf(ss);
                float beta = -copysignf(f_lapy2(alpha, xnorm), alpha);
                taui = (beta - alpha) / beta;
                float scal = 1.f / (alpha - beta);
                if (lane == 0)
                    for (int r = i + 2; r < NT; r++) As[r][i] *= scal;
                __syncwarp();
                E_(i) = beta;
                float xr = 0.f, vr = 0.f;
                if (lane >= i + 1 && lane < NT) {
                    vr = (lane == i + 1) ? 1.f : As[lane][i];
                    for (int cc = i + 1; cc < NT; cc++) {
                        float vc = (cc == i + 1) ? 1.f : As[cc][i];
                        xr += As[lane][cc] * vc;
                    }
                    xr *= taui;
                }
                float pv = (lane >= i + 1 && lane < NT) ? vr * xr : 0.f;
                for (int o = 16; o; o >>= 1) pv += __shfl_xor_sync(0xffffffffu, pv, o);
                float a2 = -0.5f * taui * pv;
                float wr = xr + a2 * vr;
                if (lane < NT) { wsh[lane] = wr; vsh[lane] = vr; }
                __syncwarp();
                if (lane >= i + 1 && lane < NT)
                    for (int cc = i + 1; cc < NT; cc++)
                        As[lane][cc] -= vr * wsh[cc] + wr * vsh[cc];
                __syncwarp();
            } else E_(i) = alpha;
        } else E_(i) = alpha;
        TAU_(i) = taui;
        D_(i) = As[i][i];
    }
    D_(NT - 1) = As[NT - 1][NT - 1];

    // ---- SSTEQR('I') ----
    const float eps = 5.9604645e-8f, eps2 = eps * eps, safmin = 1.1754944e-38f;
    int l1 = 0, jtot = 0;
    const int nmaxit = NT * 30;
    while (l1 < NT) {
        if (l1 > 0) E_(l1 - 1) = 0.f;
        int m;
        for (m = l1; m < NT - 1; m++) {
            float tst = fabsf(E_(m));
            if (tst == 0.f) break;
            if (tst <= (sqrtf(fabsf(D_(m))) * sqrtf(fabsf(D_(m + 1)))) * eps) { E_(m) = 0.f; break; }
        }
        int l = l1, lsv = l, lend = m, lendsv = lend;
        l1 = m + 1;
        if (lend == l) continue;
        if (fabsf(D_(lend)) < fabsf(D_(l))) { lend = lsv; l = lendsv; }

        if (lend > l) {
            // ---- QL ----
            for (;;) {
                if (l != lend) {
                    for (m = l; m < lend; m++) {
                        float tst = E_(m) * E_(m);
                        if (tst <= (eps2 * fabsf(D_(m))) * fabsf(D_(m + 1)) + safmin) break;
                    }
                } else m = lend;
                if (m < lend) E_(m) = 0.f;
                float p = D_(l);
                if (m == l) { D_(l) = p; l++; if (l <= lend) continue; else break; }
                if (m == l + 1) {
                    float rt1, rt2, c, s;
                    f_laev2(D_(l), E_(l), D_(l + 1), &rt1, &rt2, &c, &s);
                    if (lane < NT) {
                        float z1 = Zs[lane][l + 1], z0 = Zs[lane][l];
                        Zs[lane][l + 1] = c * z1 - s * z0;
                        Zs[lane][l]     = s * z1 + c * z0;
                    }
                    D_(l) = rt1; D_(l + 1) = rt2; E_(l) = 0.f;
                    l += 2; if (l <= lend) continue; else break;
                }
                if (jtot == nmaxit) break;
                jtot++;
                float g = (D_(l + 1) - p) / (2.f * E_(l));
                float r = f_lapy2(g, 1.f);
                g = D_(m) - p + E_(l) / (g + copysignf(r, g));
                float s = 1.f, c = 1.f;
                p = 0.f;
                float dn = D_(m);
                for (int i = m - 1; i >= l; i--) {
                    float ei = E_(i);
                    float f = s * ei, b = c * ei;
                    f_lartg(g, f, &c, &s, &r);
                    if (i != m - 1) E_(i + 1) = r;
                    g = dn - p;
                    float di = D_(i);
                    r = (di - g) * s + 2.f * c * b;
                    p = s * r;
                    D_(i + 1) = g + p;
                    g = c * r - b;
                    dn = di;
                    if (lane < NT) {
                        float z1 = Zs[lane][i + 1], z0 = Zs[lane][i];
                        Zs[lane][i + 1] =  c * z1 + s * z0;
                        Zs[lane][i]     = -s * z1 + c * z0;
                    }
                }
                D_(l) = dn - p;
                E_(l) = g;
            }
        } else {
            // ---- QR ----
            for (;;) {
                if (l != lend) {
                    for (m = l; m > lend; m--) {
                        float tst = E_(m - 1) * E_(m - 1);
                        if (tst <= (eps2 * fabsf(D_(m))) * fabsf(D_(m - 1)) + safmin) break;
                    }
                } else m = lend;
                if (m > lend) E_(m - 1) = 0.f;
                float p = D_(l);
                if (m == l) { D_(l) = p; l--; if (l >= lend) continue; else break; }
                if (m == l - 1) {
                    float rt1, rt2, c, s;
                    f_laev2(D_(l - 1), E_(l - 1), D_(l), &rt1, &rt2, &c, &s);
                    if (lane < NT) {
                        float z1 = Zs[lane][l], z0 = Zs[lane][l - 1];
                        Zs[lane][l]     = c * z1 - s * z0;
                        Zs[lane][l - 1] = s * z1 + c * z0;
                    }
                    D_(l - 1) = rt1; D_(l) = rt2; E_(l - 1) = 0.f;
                    l -= 2; if (l >= lend) continue; else break;
                }
                if (jtot == nmaxit) break;
                jtot++;
                float g = (D_(l - 1) - p) / (2.f * E_(l - 1));
                float r = f_lapy2(g, 1.f);
                g = D_(m) - p + E_(l - 1) / (g + copysignf(r, g));
                float s = 1.f, c = 1.f;
                p = 0.f;
                float dc = D_(m);
                for (int i = m; i <= l - 1; i++) {
                    float ei = E_(i);
                    float f = s * ei, b = c * ei;
                    f_lartg(g, f, &c, &s, &r);
                    if (i != m) E_(i - 1) = r;
                    g = dc - p;
                    float dip = D_(i + 1);
                    r = (dip - g) * s + 2.f * c * b;
                    p = s * r;
                    D_(i) = g + p;
                    g = c * r - b;
                    dc = dip;
                    if (lane < NT) {
                        float z1 = Zs[lane][i + 1], z0 = Zs[lane][i];
                        Zs[lane][i + 1] = c * z1 - s * z0;
                        Zs[lane][i]     = s * z1 + c * z0;
                    }
                }
                D_(l) = dc - p;
                E_(l - 1) = g;
            }
        }
    }

    // ---- eigen sort ascending ----
    for (int ii = 1; ii < NT; ii++) {
        int i = ii - 1, k = i;
        float p = D_(i);
        for (int j = ii; j < NT; j++) if (D_(j) < p) { k = j; p = D_(j); }
        if (k != i) {
            D_(k) = D_(i); D_(i) = p;
            if (lane < NT) { float tm = Zs[lane][i]; Zs[lane][i] = Zs[lane][k]; Zs[lane][k] = tm; }
        }
    }
    __syncwarp();

    // ---- SORMTR('L','L','N') ----
    if (lane < NT) {
        int j = lane;
        for (int i = NT - 2; i >= 0; i--) {
            float ti = TAU_(i);
            if (ti == 0.f) continue;
            float w = Zs[i + 1][j];
            for (int r = i + 2; r < NT; r++) w += As[r][i] * Zs[r][j];
            w *= ti;
            Zs[i + 1][j] -= w;
            for (int r = i + 2; r < NT; r++) Zs[r][j] -= As[r][i] * w;
        }
    }
    __syncwarp();

    if (lane < NT) g_s[lane] = D_(lane);
    for (int idx = lane; idx < NT * NT; idx += 32) g_U[idx] = Zs[idx / NT][idx % NT];

    // ---- A = Kfc @ U ----
    for (int idx = lane; idx < NT * NT; idx += 32) {
        int f = idx / NT, l2 = idx % NT;
        float tf = (float)(NT + f) * PICF;
        float acc = 0.f;
        for (int i2 = 0; i2 < NT; i2++)
            acc += expf(-fabsf(tf - (float)i2 * PICF)) * Zs[i2][l2];
        Aq[f][l2] = acc;
        g_A[idx] = acc;
    }
    __syncwarp();

    // ---- Wm ----
    for (int idx = lane; idx < NT * NT * 25; idx += 32) {
        int fg = idx / 25, i2 = idx % 25;
        int f = fg / NT, g2 = fg % NT;
        g_Wm[idx] = (i2 == 24) ? expf(-fabsf((float)(NT + f) * PICF - (float)(NT + g2) * PICF))
                               : -Aq[f][i2] * Aq[g2][i2];
    }
#undef D_
#undef E_
#undef TAU_
}

// ---------------- K0: Bt = V V^T + diag(task_var) ----------------
__global__ void k_bt(const float* __restrict__ V, const float* __restrict__ tv) {
    int idx = blockIdx.x * 256 + threadIdx.x;
    int c = idx >> 7, d = idx & 127;
    float acc = (c == d) ? tv[c] : 0.f;
#pragma unroll
    for (int k = 0; k < NR; k++) acc += V[c * NR + k] * V[d * NR + k];
    g_Bt[idx] = acc;
}

// ---------------- K2: low-rank factors per i -------------------------------
__global__ void k_wood(const float* __restrict__ Vg, const float* __restrict__ tv) {
    int i = blockIdx.x;       // 24 blocks
    int c = threadIdx.x;      // 128 threads
    __shared__ float Vs[NC][NR];
    __shared__ float Wsh[NC][NR];
    __shared__ float Ssm[NR][NR];
    __shared__ float Sinv[NR][NR];

    float si  = g_s[i];
    float eps = SIG2 / si;
    float dinv = 1.f / (tv[c] + eps);

    float w[NR];
#pragma unroll
    for (int k = 0; k < NR; k++) {
        float v = Vg[c * NR + k];
        Vs[c][k] = v;
        w[k] = v * dinv;
        Wsh[c][k] = w[k];
    }
    __syncthreads();

    if (c < NR * NR) {
        int k = c >> 3, l = c & 7;
        float acc = 0.f;
        for (int e = 0; e < NC; e++) acc += Vs[e][k] * Wsh[e][l];
        Ssm[k][l] = ((k == l) ? 1.f : 0.f) + acc;
    }
    __syncthreads();
    if (c == 0) {
        float M[NR][2 * NR];
        for (int r = 0; r < NR; r++)
            for (int c2 = 0; c2 < NR; c2++) {
                M[r][c2] = Ssm[r][c2];
                M[r][NR + c2] = (r == c2) ? 1.f : 0.f;
            }
        for (int p = 0; p < NR; p++) {
            float piv = 1.f / M[p][p];
            for (int c2 = 0; c2 < 2 * NR; c2++) M[p][c2] *= piv;
            for (int r = 0; r < NR; r++) {
                if (r == p) continue;
                float fct = M[r][p];
                for (int c2 = 0; c2 < 2 * NR; c2++) M[r][c2] -= fct * M[p][c2];
            }
        }
        for (int r = 0; r < NR; r++)
            for (int c2 = 0; c2 < NR; c2++) Sinv[r][c2] = M[r][NR + c2];
    }
    __syncthreads();

    float z[NR];
#pragma unroll
    for (int k = 0; k < NR; k++) {
        float acc = 0.f;
#pragma unroll
        for (int l = 0; l < NR; l++) acc += w[l] * Sinv[l][k];
        z[k] = acc;
    }
    int base = i * NC * NR + c * NR;
#pragma unroll
    for (int k = 0; k < NR; k++) { g_W[base + k] = w[k]; g_Z[base + k] = z[k]; }
    g_gamma[i * NC + c] = (-eps + eps * eps * dinv) / si;
}

// ---------------- K3: G_i = alpha*Bt + gamma*I - beta * Z W^T ---------------
__global__ void k_G() {
    int i = blockIdx.x;
    int cb = blockIdx.y;
    int tid = threadIdx.x;  // 256
    __shared__ float Wsh[NC][NR + 1];
    __shared__ float gam[NC];
    for (int idx = tid; idx < NC * NR; idx += 256)
        Wsh[idx >> 3][idx & 7] = g_W[i * NC * NR + idx];
    for (int idx = tid; idx < NC; idx += 256) gam[idx] = g_gamma[i * NC + idx];
    __syncthreads();

    float si = g_s[i];
    float eps = SIG2 / si;
    float alpha = 1.f / si;
    float beta = eps * eps / si;

    int c  = cb * 32 + (tid >> 3);
    int dg = (tid & 7) * 16;
    float z[NR];
#pragma unroll
    for (int k = 0; k < NR; k++) z[k] = g_Z[i * NC * NR + c * NR + k];

    const float4* btp = reinterpret_cast<const float4*>(&g_Bt[c * NC + dg]);
    float4* gout = reinterpret_cast<float4*>(&g_G[(i * NC + c) * NC + dg]);
#pragma unroll
    for (int v = 0; v < 4; v++) {
        float4 b = btp[v];
        float o[4];
#pragma unroll
        for (int e = 0; e < 4; e++) {
            int d = dg + v * 4 + e;
            float dot = 0.f;
#pragma unroll
            for (int k = 0; k < NR; k++) dot += z[k] * Wsh[d][k];
            float val = alpha * ((const float*)&b)[e] - beta * dot;
            if (d == c) val += gam[c];
            o[e] = val;
        }
        gout[v] = make_float4(o[0], o[1], o[2], o[3]);
    }
}

// ---------------- K4: mean (low-rank R) -------------------------------------
__global__ void k_mean(const float* __restrict__ x, const float* __restrict__ tv,
                       float* __restrict__ out) {
    int b = blockIdx.x, tid = threadIdx.x;  // 128
    __shared__ float Ys[NT][NC];
    __shared__ float Ts[NT][NC];
    __shared__ float Q[NT][NC];
    __shared__ float Us[NT][NT];
    __shared__ float hsh[NR];

    for (int idx = tid; idx < NT * NT; idx += 128) Us[idx / NT][idx % NT] = g_U[idx];
    float tvd = tv[tid];

    const float* xr = x + (size_t)(b * NC + tid) * NL;
    float xv[NL];
#pragma unroll
    for (int l = 0; l < NL; l++) xv[l] = xr[l];
#pragma unroll
    for (int j = 0; j < NT; j++) {
        int h = j >> 1;
        Ys[j][tid] = xv[NT + j] - 0.5f * (xv[12 + h] + xv[36 + h]);
    }
    __syncthreads();

#pragma unroll 1
    for (int i = 0; i < NT; i++) {
        float acc = 0.f;
#pragma unroll
        for (int j = 0; j < NT; j++) acc += Us[i][j] * Ys[j][tid];
        Ts[i][tid] = acc;
    }
    __syncthreads();

    int kk = tid >> 4, j0 = tid & 15;
#pragma unroll 1
    for (int i = 0; i < NT; i++) {
        float si = g_s[i];
        float eps = SIG2 / si;
        float a1 = 1.f / si;
        float q3 = eps / si;
        float part = 0.f;
#pragma unroll
        for (int t = 0; t < 8; t++) {
            int cc = j0 + 16 * t;
            part += g_W[i * NC * NR + cc * NR + kk] * Ts[i][cc];
        }
#pragma unroll
        for (int off = 8; off; off >>= 1)
            part += __shfl_down_sync(0xffffffffu, part, off, 16);
        if (j0 == 0) hsh[kk] = part;
        __syncthreads();

        float T = Ts[i][tid];
        float dinv = 1.f / (tvd + eps);
        float zh = 0.f;
#pragma unroll
        for (int k2 = 0; k2 < NR; k2++)
            zh += g_Z[i * NC * NR + tid * NR + k2] * hsh[k2];
        Q[i][tid] = a1 * T - q3 * T * dinv + q3 * zh;
        __syncthreads();
    }

#pragma unroll 1
    for (int f = 0; f < NT; f++) {
        float acc = 0.f;
#pragma unroll
        for (int i = 0; i < NT; i++) acc += g_A[f * NT + i] * Q[i][tid];
        acc += 0.5f * (xv[f] + xv[NT + f]);
        out[(size_t)(b * NT + f) * NC + tid] = acc;
    }
}

// ---------------- K5: covariance, broadcast 8 batches -----------------------
__global__ void __launch_bounds__(256, 1) k_cov(float* __restrict__ out) {
    float* cov = out + MEAN_ELEMS;
    int patch = blockIdx.x;
    int fgBase = blockIdx.y * 16;
    int tid = threadIdx.x;

    __shared__ float Wsm[16 * 25];
    for (int idx = tid; idx < 16 * 25; idx += 256) Wsm[idx] = g_Wm[fgBase * 25 + idx];

    int c  = (patch >> 2) * 32 + (tid >> 3);
    int d0 = (patch & 3) * 32 + (tid & 7) * 4;

    float4 bt = *reinterpret_cast<const float4*>(&g_Bt[c * NC + d0]);
    float4 gg[NT];
#pragma unroll
    for (int i = 0; i < NT; i++)
        gg[i] = *reinterpret_cast<const float4*>(&g_G[(i * NC + c) * NC + d0]);
    __syncthreads();

#pragma unroll 1
    for (int t = 0; t < 16; t++) {
        int fg = fgBase + t;
        int f = fg / NT, g = fg % NT;
        const float* w = &Wsm[t * 25];
        float w24 = w[24];
        float4 acc;
        acc.x = w24 * bt.x; acc.y = w24 * bt.y; acc.z = w24 * bt.z; acc.w = w24 * bt.w;
#pragma unroll
        for (int i = 0; i < NT; i++) {
            float wi = w[i];
            acc.x += wi * gg[i].x;
            acc.y += wi * gg[i].y;
            acc.z += wi * gg[i].z;
            acc.w += wi * gg[i].w;
        }
        if (f == g && c >= d0 && c < d0 + 4)
            reinterpret_cast<float*>(&acc)[c - d0] += SIG2;
        size_t row = (size_t)(f * NC + c);
        size_t col = (size_t)(g * NC + d0);
        float* p = cov + row * COV_N + col;
#pragma unroll
        for (int b = 0; b < NB; b++) {
            __stcs(reinterpret_cast<float4*>(p), acc);
            p += COV_ELEMS;
        }
    }
}

// ---------------- launcher ---------------------------------------------------
extern "C" void kernel_launch(void* const* d_in, const int* in_sizes, int n_in,
                              void* d_out, int out_size) {
    const float* x  = (const float*)d_in[0];
    const float* V  = (const float*)d_in[1];
    const float* tv = (const float*)d_in[2];
    float* out = (float*)d_out;

    k_bt<<<64, 256>>>(V, tv);
    k_eig<<<1, 32>>>();
    k_wood<<<24, 128>>>(V, tv);
    k_G<<<dim3(24, 4), 256>>>();
    k_mean<<<8, 128>>>(x, tv, out);
    k_cov<<<dim3(16, 36), 256>>>(out);
}

// round 16
// speedup vs baseline: 5.1850x; 2.7865x over previous
#include <cuda_runtime.h>
#include <cuda_bf16.h>
#include <math.h>

#define NB   8
#define NC   128
#define NL   48
#define NT   24
#define NR   8
#define SIG2 1.0001f
#define PICF ((float)(3.14159265358979323846 / 24.0))

#define COV_N      3072
#define COV_ELEMS  9437184ull
#define MEAN_ELEMS 24576

// ============================================================================
// Compile-time eigendecomposition of the CONSTANT matrix
// Kc[i][j] = exp(-pi/24*|i-j|), LAPACK ssyevd path (ssytd2 -> ssteqr('I') ->
// sort -> sormtr), with PER-OPERATION fp32 rounding emulated in constexpr
// double (r32 = round-to-float + FTZ). This reproduces the R11/R13-passing
// fp32 trajectory to within ulps (the validated robustness envelope), unlike
// the plain-fp64 R15 attempt whose 1e-7 drift flipped eigenvector signs.
// FTZ only diverges from device fp32 in Z (eigenvector) entries, which never
// feed the d/e branch decisions.
// ============================================================================

struct EigData {
    float U[NT * NT];
    float s[NT];
    float A[NT * NT];
    float Wm[NT * NT * 25];
};

__host__ __device__ constexpr double cfabsd(double x) { return x < 0.0 ? -x : x; }
__host__ __device__ constexpr double ccopysignd(double m, double s) {
    double a = m < 0.0 ? -m : m;
    return s >= 0.0 ? a : -a;
}

// round double -> nearest fp32 (as double), flush |x| < FLT_MIN to 0.
__host__ __device__ constexpr double r32(double x) {
    double ax = x < 0.0 ? -x : x;
    if (ax < 1.1754943508222875e-38) return 0.0;
    return (double)(float)x;
}
__host__ __device__ constexpr double rm(double a, double b) { return r32(a * b); }
__host__ __device__ constexpr double ra(double a, double b) { return r32(a + b); }
__host__ __device__ constexpr double rsb(double a, double b) { return r32(a - b); }
__host__ __device__ constexpr double rd(double a, double b) { return r32(a / b); }

// sqrt in double (scaled Newton, 8 iters -> ~1e-15 rel)
__host__ __device__ constexpr double csq(double x) {
    if (x <= 0.0) return 0.0;
    double sc = 1.0, y = x;
    while (y >= 4.0)  { y *= 0.25; sc *= 2.0; }
    while (y < 0.25)  { y *= 4.0;  sc *= 0.5; }
    double g = 1.0;
    for (int i = 0; i < 8; i++) g = 0.5 * (g + y / g);
    return sc * g;
}
// fp32-rounded sqrt of an fp32-valued input
__host__ __device__ constexpr double rsq(double x) { return r32(csq(x)); }

// exp(x), |x| < 8, double internal; callers wrap r32.
__host__ __device__ constexpr double cexp_(double x) {
    const double LN2 = 0.69314718055994530941723212145818;
    double kd = x / LN2;
    int k = (int)(kd >= 0.0 ? kd + 0.5 : kd - 0.5);
    double r = x - (double)k * LN2;
    double t = 1.0, s = 1.0;
    for (int i = 1; i <= 15; i++) { t = t * r / (double)i; s += t; }
    double p = 1.0;
    int kk = k < 0 ? -k : k;
    for (int i = 0; i < kk; i++) p *= 2.0;
    return k < 0 ? s / p : s * p;
}

// fp32-faithful lapy2: w*sqrt(1+(z/w)^2)
__host__ __device__ constexpr double c_lapy2(double x, double y) {
    double ax = cfabsd(x), ay = cfabsd(y);
    double w = ax > ay ? ax : ay;
    double z = ax > ay ? ay : ax;
    if (z == 0.0) return w;
    double q = rd(z, w);
    double arg = ra(1.0, rm(q, q));
    return rm(w, rsq(arg));
}

struct Rot { double c, s, r; };
// fp32-faithful slartg (LAPACK >=3.10, sqrt form as in passing R11)
__host__ __device__ constexpr Rot c_lartg(double f, double g) {
    Rot o{1.0, 0.0, f};
    if (g == 0.0) { o.c = 1.0; o.s = 0.0; o.r = f; }
    else if (f == 0.0) { o.c = 0.0; o.s = (g > 0.0 ? 1.0 : -1.0); o.r = cfabsd(g); }
    else {
        double t2 = ra(rm(f, f), rm(g, g));
        double d = rsq(t2);
        o.c = rd(cfabsd(f), d);
        o.r = ccopysignd(d, f);
        o.s = rd(g, o.r);
    }
    return o;
}

struct Ev2 { double rt1, rt2, cs1, sn1; };
__host__ __device__ constexpr Ev2 c_laev2(double a, double b, double c) {
    Ev2 o{0.0, 0.0, 1.0, 0.0};
    double sm = ra(a, c), df = rsb(a, c), adf = cfabsd(df);
    double tb = ra(b, b), ab = cfabsd(tb);
    double acmx = 0.0, acmn = 0.0;
    if (cfabsd(a) > cfabsd(c)) { acmx = a; acmn = c; } else { acmx = c; acmn = a; }
    double rt = 0.0;
    if (adf > ab)      { double q = rd(ab, adf); rt = rm(adf, rsq(ra(1.0, rm(q, q)))); }
    else if (adf < ab) { double q = rd(adf, ab); rt = rm(ab, rsq(ra(1.0, rm(q, q)))); }
    else               rt = rm(ab, rsq(2.0));
    int sgn1 = 1;
    if (sm < 0.0) {
        o.rt1 = rm(0.5, rsb(sm, rt)); sgn1 = -1;
        o.rt2 = rsb(rm(rd(acmx, o.rt1), acmn), rm(rd(b, o.rt1), b));
    } else if (sm > 0.0) {
        o.rt1 = rm(0.5, ra(sm, rt)); sgn1 = 1;
        o.rt2 = rsb(rm(rd(acmx, o.rt1), acmn), rm(rd(b, o.rt1), b));
    } else { o.rt1 = rm(0.5, rt); o.rt2 = rm(-0.5, rt); sgn1 = 1; }
    int sgn2 = 1; double cs = 0.0;
    if (df >= 0.0) { cs = ra(df, rt); sgn2 = 1; } else { cs = rsb(df, rt); sgn2 = -1; }
    double acs = cfabsd(cs);
    if (acs > ab) {
        double ct = rd(-tb, cs);
        o.sn1 = rd(1.0, rsq(ra(1.0, rm(ct, ct))));
        o.cs1 = rm(ct, o.sn1);
    } else {
        if (ab == 0.0) { o.cs1 = 1.0; o.sn1 = 0.0; }
        else {
            double tn = rd(-cs, tb);
            o.cs1 = rd(1.0, rsq(ra(1.0, rm(tn, tn))));
            o.sn1 = rm(tn, o.cs1);
        }
    }
    if (sgn1 == sgn2) { double tn = o.cs1; o.cs1 = -o.sn1; o.sn1 = tn; }
    return o;
}

__host__ __device__ constexpr EigData make_eig() {
    EigData E = {};
    const double TH = (double)PICF;   // fp32 grid step, exact in double
    double As[NT][NT] = {};
    double Zs[NT][NT] = {};
    double d[NT] = {}, e[NT] = {}, tau[NT] = {};

    // fp32 grid + fp32-rounded exp (matches device expf to <=1-2 ulp)
    for (int i = 0; i < NT; i++) {
        double ti = rm((double)i, TH);
        for (int j = 0; j < NT; j++) {
            double tj = rm((double)j, TH);
            As[i][j] = r32(cexp_(-cfabsd(rsb(ti, tj))));
            Zs[i][j] = (i == j) ? 1.0 : 0.0;
        }
    }

    // ---- SSYTD2 (lower), fp32-rounded per op ----
    for (int i = 0; i < NT - 1; i++) {
        double alpha = As[i + 1][i];
        double taui = 0.0;
        if (i < NT - 2) {
            double ss = 0.0;
            for (int r = i + 2; r < NT; r++) ss = ra(ss, rm(As[r][i], As[r][i]));
            if (ss != 0.0) {
                double xnorm = rsq(ss);
                double beta = -ccopysignd(c_lapy2(alpha, xnorm), alpha);
                taui = rd(rsb(beta, alpha), beta);
                double scal = rd(1.0, rsb(alpha, beta));
                for (int r = i + 2; r < NT; r++) As[r][i] = rm(As[r][i], scal);
                e[i] = beta;
                double xr_[NT] = {}, vr_[NT] = {}, wsh[NT] = {};
                for (int lane = i + 1; lane < NT; lane++) {
                    double vr = (lane == i + 1) ? 1.0 : As[lane][i];
                    double acc = 0.0;
                    for (int cc = i + 1; cc < NT; cc++) {
                        double vc = (cc == i + 1) ? 1.0 : As[cc][i];
                        acc = ra(acc, rm(As[lane][cc], vc));
                    }
                    xr_[lane] = rm(acc, taui);
                    vr_[lane] = vr;
                }
                // butterfly reduction (replicates __shfl_xor order of R13)
                double red[32] = {};
                for (int lane = i + 1; lane < NT; lane++) red[lane] = rm(vr_[lane], xr_[lane]);
                for (int o = 16; o; o >>= 1) {
                    double tmp[32] = {};
                    for (int j = 0; j < 32; j++) tmp[j] = ra(red[j], red[j ^ o]);
                    for (int j = 0; j < 32; j++) red[j] = tmp[j];
                }
                double pv = red[0];
                double a2 = rm(rm(-0.5, taui), pv);
                for (int lane = i + 1; lane < NT; lane++)
                    wsh[lane] = ra(xr_[lane], rm(a2, vr_[lane]));
                for (int lane = i + 1; lane < NT; lane++)
                    for (int cc = i + 1; cc < NT; cc++)
                        As[lane][cc] = rsb(As[lane][cc],
                                           ra(rm(vr_[lane], wsh[cc]), rm(wsh[lane], vr_[cc])));
            } else e[i] = alpha;
        } else e[i] = alpha;
        tau[i] = taui;
        d[i] = As[i][i];
    }
    d[NT - 1] = As[NT - 1][NT - 1];

    // ---- SSTEQR('I'), fp32-rounded per op ----
    const double eps = 5.9604645e-8, eps2 = 3.5527137e-15, safmin = 1.1754944e-38;
    int l1 = 0, jtot = 0;
    const int nmaxit = NT * 30;
    while (l1 < NT) {
        if (l1 > 0) e[l1 - 1] = 0.0;
        int m = l1;
        for (m = l1; m < NT - 1; m++) {
            double tst = cfabsd(e[m]);
            if (tst == 0.0) break;
            if (tst <= rm(rm(rsq(cfabsd(d[m])), rsq(cfabsd(d[m + 1]))), eps)) { e[m] = 0.0; break; }
        }
        int l = l1, lsv = l, lend = m, lendsv = lend;
        l1 = m + 1;
        if (lend == l) continue;
        if (cfabsd(d[lend]) < cfabsd(d[l])) { lend = lsv; l = lendsv; }

        if (lend > l) {
            // ---- QL ----
            for (;;) {
                if (l != lend) {
                    for (m = l; m < lend; m++) {
                        double tst = rm(e[m], e[m]);
                        if (tst <= ra(rm(rm(eps2, cfabsd(d[m])), cfabsd(d[m + 1])), safmin)) break;
                    }
                } else m = lend;
                if (m < lend) e[m] = 0.0;
                double p = d[l];
                if (m == l) { d[l] = p; l++; if (l <= lend) continue; else break; }
                if (m == l + 1) {
                    Ev2 v = c_laev2(d[l], e[l], d[l + 1]);
                    for (int lane = 0; lane < NT; lane++) {
                        double z1 = Zs[lane][l + 1], z0 = Zs[lane][l];
                        Zs[lane][l + 1] = rsb(rm(v.cs1, z1), rm(v.sn1, z0));
                        Zs[lane][l]     = ra(rm(v.sn1, z1), rm(v.cs1, z0));
                    }
                    d[l] = v.rt1; d[l + 1] = v.rt2; e[l] = 0.0;
                    l += 2; if (l <= lend) continue; else break;
                }
                if (jtot == nmaxit) break;
                jtot++;
                double g = rd(rsb(d[l + 1], p), rm(2.0, e[l]));
                double r = c_lapy2(g, 1.0);
                g = ra(rsb(d[m], p), rd(e[l], ra(g, ccopysignd(r, g))));
                double s = 1.0, c = 1.0;
                p = 0.0;
                double dn = d[m];
                for (int i2 = m - 1; i2 >= l; i2--) {
                    double ei = e[i2];
                    double f = rm(s, ei), b = rm(c, ei);
                    Rot ro = c_lartg(g, f);
                    c = ro.c; s = ro.s; r = ro.r;
                    if (i2 != m - 1) e[i2 + 1] = r;
                    g = rsb(dn, p);
                    double di = d[i2];
                    r = ra(rm(rsb(di, g), s), rm(rm(2.0, c), b));
                    p = rm(s, r);
                    d[i2 + 1] = ra(g, p);
                    g = rsb(rm(c, r), b);
                    dn = di;
                    for (int lane = 0; lane < NT; lane++) {
                        double z1 = Zs[lane][i2 + 1], z0 = Zs[lane][i2];
                        Zs[lane][i2 + 1] = ra(rm(c, z1), rm(s, z0));
                        Zs[lane][i2]     = rsb(rm(c, z0), rm(s, z1));
                    }
                }
                d[l] = rsb(dn, p);
                e[l] = g;
            }
        } else {
            // ---- QR ----
            for (;;) {
                if (l != lend) {
                    for (m = l; m > lend; m--) {
                        double tst = rm(e[m - 1], e[m - 1]);
                        if (tst <= ra(rm(rm(eps2, cfabsd(d[m])), cfabsd(d[m - 1])), safmin)) break;
                    }
                } else m = lend;
                if (m > lend) e[m - 1] = 0.0;
                double p = d[l];
                if (m == l) { d[l] = p; l--; if (l >= lend) continue; else break; }
                if (m == l - 1) {
                    Ev2 v = c_laev2(d[l - 1], e[l - 1], d[l]);
                    for (int lane = 0; lane < NT; lane++) {
                        double z1 = Zs[lane][l], z0 = Zs[lane][l - 1];
                        Zs[lane][l]     = rsb(rm(v.cs1, z1), rm(v.sn1, z0));
                        Zs[lane][l - 1] = ra(rm(v.sn1, z1), rm(v.cs1, z0));
                    }
                    d[l - 1] = v.rt1; d[l] = v.rt2; e[l - 1] = 0.0;
                    l -= 2; if (l >= lend) continue; else break;
                }
                if (jtot == nmaxit) break;
                jtot++;
                double g = rd(rsb(d[l - 1], p), rm(2.0, e[l - 1]));
                double r = c_lapy2(g, 1.0);
                g = ra(rsb(d[m], p), rd(e[l - 1], ra(g, ccopysignd(r, g))));
                double s = 1.0, c = 1.0;
                p = 0.0;
                double dc = d[m];
                for (int i2 = m; i2 <= l - 1; i2++) {
                    double ei = e[i2];
                    double f = rm(s, ei), b = rm(c, ei);
                    Rot ro = c_lartg(g, f);
                    c = ro.c; s = ro.s; r = ro.r;
                    if (i2 != m) e[i2 - 1] = r;
                    g = rsb(dc, p);
                    double dip = d[i2 + 1];
                    r = ra(rm(rsb(dip, g), s), rm(rm(2.0, c), b));
                    p = rm(s, r);
                    d[i2] = ra(g, p);
                    g = rsb(rm(c, r), b);
                    dc = dip;
                    for (int lane = 0; lane < NT; lane++) {
                        double z1 = Zs[lane][i2 + 1], z0 = Zs[lane][i2];
                        Zs[lane][i2 + 1] = rsb(rm(c, z1), rm(s, z0));
                        Zs[lane][i2]     = ra(rm(s, z1), rm(c, z0));
                    }
                }
                d[l] = rsb(dc, p);
                e[l - 1] = g;
            }
        }
    }

    // ---- sort ascending (LAPACK selection sort) ----
    for (int ii = 1; ii < NT; ii++) {
        int i = ii - 1, k = i;
        double p = d[i];
        for (int j = ii; j < NT; j++) if (d[j] < p) { k = j; p = d[j]; }
        if (k != i) {
            d[k] = d[i]; d[i] = p;
            for (int lane = 0; lane < NT; lane++) {
                double tm = Zs[lane][i]; Zs[lane][i] = Zs[lane][k]; Zs[lane][k] = tm;
            }
        }
    }

    // ---- SORMTR('L','L','N'), fp32-rounded ----
    for (int j = 0; j < NT; j++) {
        for (int i = NT - 2; i >= 0; i--) {
            double ti = tau[i];
            if (ti == 0.0) continue;
            double w = Zs[i + 1][j];
            for (int r = i + 2; r < NT; r++) w = ra(w, rm(As[r][i], Zs[r][j]));
            w = rm(w, ti);
            Zs[i + 1][j] = rsb(Zs[i + 1][j], w);
            for (int r = i + 2; r < NT; r++) Zs[r][j] = rsb(Zs[r][j], rm(As[r][i], w));
        }
    }

    for (int i = 0; i < NT; i++) E.s[i] = (float)d[i];
    for (int i = 0; i < NT; i++)
        for (int j = 0; j < NT; j++) E.U[i * NT + j] = (float)Zs[i][j];

    // ---- A = Kfc @ U (fp32 grid / rounded exp) ----
    double kfc[NT][NT] = {};
    for (int f = 0; f < NT; f++) {
        double tf = rm((double)(NT + f), TH);
        for (int i2 = 0; i2 < NT; i2++) {
            double ti2 = rm((double)i2, TH);
            kfc[f][i2] = r32(cexp_(-cfabsd(rsb(tf, ti2))));
        }
    }
    double Aq[NT][NT] = {};
    for (int f = 0; f < NT; f++)
        for (int l2 = 0; l2 < NT; l2++) {
            double acc = 0.0;
            for (int i2 = 0; i2 < NT; i2++) acc = ra(acc, rm(kfc[f][i2], Zs[i2][l2]));
            Aq[f][l2] = acc;
            E.A[f * NT + l2] = (float)acc;
        }

    // ---- Wm ----
    for (int fg = 0; fg < NT * NT; fg++) {
        int f = fg / NT, g2 = fg % NT;
        for (int i2 = 0; i2 < 25; i2++) {
            double v = 0.0;
            if (i2 == 24) {
                double tf = rm((double)(NT + f), TH), tg = rm((double)(NT + g2), TH);
                v = r32(cexp_(-cfabsd(rsb(tf, tg))));
            } else v = -rm(Aq[f][i2], Aq[g2][i2]);
            E.Wm[fg * 25 + i2] = (float)v;
        }
    }
    return E;
}

__device__ constexpr EigData EIG = make_eig();

// ============================================================================
// Runtime scratch + kernels (byte-identical to the R13-passing versions)
// ============================================================================
__device__ float g_Bt[NC * NC];
__device__ float g_W[NT * NC * NR];
__device__ float g_Z[NT * NC * NR];
__device__ float g_gamma[NT * NC];
__device__ float g_G[NT * NC * NC];

// ---------------- K0: Bt = V V^T + diag(task_var) ----------------
__global__ void k_bt(const float* __restrict__ V, const float* __restrict__ tv) {
    int idx = blockIdx.x * 256 + threadIdx.x;
    int c = idx >> 7, d = idx & 127;
    float acc = (c == d) ? tv[c] : 0.f;
#pragma unroll
    for (int k = 0; k < NR; k++) acc += V[c * NR + k] * V[d * NR + k];
    g_Bt[idx] = acc;
}

// ---------------- K2: low-rank factors per i -------------------------------
__global__ void k_wood(const float* __restrict__ Vg, const float* __restrict__ tv) {
    int i = blockIdx.x;       // 24 blocks
    int c = threadIdx.x;      // 128 threads
    __shared__ float Vs[NC][NR];
    __shared__ float Wsh[NC][NR];
    __shared__ float Ssm[NR][NR];
    __shared__ float Sinv[NR][NR];

    float si  = EIG.s[i];
    float eps = SIG2 / si;
    float dinv = 1.f / (tv[c] + eps);

    float w[NR];
#pragma unroll
    for (int k = 0; k < NR; k++) {
        float v = Vg[c * NR + k];
        Vs[c][k] = v;
        w[k] = v * dinv;
        Wsh[c][k] = w[k];
    }
    __syncthreads();

    if (c < NR * NR) {
        int k = c >> 3, l = c & 7;
        float acc = 0.f;
        for (int e = 0; e < NC; e++) acc += Vs[e][k] * Wsh[e][l];
        Ssm[k][l] = ((k == l) ? 1.f : 0.f) + acc;
    }
    __syncthreads();
    if (c == 0) {
        float M[NR][2 * NR];
        for (int r = 0; r < NR; r++)
            for (int c2 = 0; c2 < NR; c2++) {
                M[r][c2] = Ssm[r][c2];
                M[r][NR + c2] = (r == c2) ? 1.f : 0.f;
            }
        for (int p = 0; p < NR; p++) {
            float piv = 1.f / M[p][p];
            for (int c2 = 0; c2 < 2 * NR; c2++) M[p][c2] *= piv;
            for (int r = 0; r < NR; r++) {
                if (r == p) continue;
                float fct = M[r][p];
                for (int c2 = 0; c2 < 2 * NR; c2++) M[r][c2] -= fct * M[p][c2];
            }
        }
        for (int r = 0; r < NR; r++)
            for (int c2 = 0; c2 < NR; c2++) Sinv[r][c2] = M[r][NR + c2];
    }
    __syncthreads();

    float z[NR];
#pragma unroll
    for (int k = 0; k < NR; k++) {
        float acc = 0.f;
#pragma unroll
        for (int l = 0; l < NR; l++) acc += w[l] * Sinv[l][k];
        z[k] = acc;
    }
    int base = i * NC * NR + c * NR;
#pragma unroll
    for (int k = 0; k < NR; k++) { g_W[base + k] = w[k]; g_Z[base + k] = z[k]; }
    g_gamma[i * NC + c] = (-eps + eps * eps * dinv) / si;
}

// ---------------- K3: G_i = alpha*Bt + gamma*I - beta * Z W^T ---------------
__global__ void k_G() {
    int i = blockIdx.x;
    int cb = blockIdx.y;
    int tid = threadIdx.x;  // 256
    __shared__ float Wsh[NC][NR + 1];
    __shared__ float gam[NC];
    for (int idx = tid; idx < NC * NR; idx += 256)
        Wsh[idx >> 3][idx & 7] = g_W[i * NC * NR + idx];
    for (int idx = tid; idx < NC; idx += 256) gam[idx] = g_gamma[i * NC + idx];
    __syncthreads();

    float si = EIG.s[i];
    float eps = SIG2 / si;
    float alpha = 1.f / si;
    float beta = eps * eps / si;

    int c  = cb * 32 + (tid >> 3);
    int dg = (tid & 7) * 16;
    float z[NR];
#pragma unroll
    for (int k = 0; k < NR; k++) z[k] = g_Z[i * NC * NR + c * NR + k];

    const float4* btp = reinterpret_cast<const float4*>(&g_Bt[c * NC + dg]);
    float4* gout = reinterpret_cast<float4*>(&g_G[(i * NC + c) * NC + dg]);
#pragma unroll
    for (int v = 0; v < 4; v++) {
        float4 b = btp[v];
        float o[4];
#pragma unroll
        for (int e = 0; e < 4; e++) {
            int d = dg + v * 4 + e;
            float dot = 0.f;
#pragma unroll
            for (int k = 0; k < NR; k++) dot += z[k] * Wsh[d][k];
            float val = alpha * ((const float*)&b)[e] - beta * dot;
            if (d == c) val += gam[c];
            o[e] = val;
        }
        gout[v] = make_float4(o[0], o[1], o[2], o[3]);
    }
}

// ---------------- K4: mean (low-rank R) -------------------------------------
__global__ void k_mean(const float* __restrict__ x, const float* __restrict__ tv,
                       float* __restrict__ out) {
    int b = blockIdx.x, tid = threadIdx.x;  // 128
    __shared__ float Ys[NT][NC];
    __shared__ float Ts[NT][NC];
    __shared__ float Q[NT][NC];
    __shared__ float Us[NT][NT];
    __shared__ float hsh[NR];

    for (int idx = tid; idx < NT * NT; idx += 128) Us[idx / NT][idx % NT] = EIG.U[idx];
    float tvd = tv[tid];

    const float* xr = x + (size_t)(b * NC + tid) * NL;
    float xv[NL];
#pragma unroll
    for (int l = 0; l < NL; l++) xv[l] = xr[l];
#pragma unroll
    for (int j = 0; j < NT; j++) {
        int h = j >> 1;
        Ys[j][tid] = xv[NT + j] - 0.5f * (xv[12 + h] + xv[36 + h]);
    }
    __syncthreads();

#pragma unroll 1
    for (int i = 0; i < NT; i++) {
        float acc = 0.f;
#pragma unroll
        for (int j = 0; j < NT; j++) acc += Us[i][j] * Ys[j][tid];
        Ts[i][tid] = acc;
    }
    __syncthreads();

    int kk = tid >> 4, j0 = tid & 15;
#pragma unroll 1
    for (int i = 0; i < NT; i++) {
        float si = EIG.s[i];
        float eps = SIG2 / si;
        float a1 = 1.f / si;
        float q3 = eps / si;
        float part = 0.f;
#pragma unroll
        for (int t = 0; t < 8; t++) {
            int cc = j0 + 16 * t;
            part += g_W[i * NC * NR + cc * NR + kk] * Ts[i][cc];
        }
#pragma unroll
        for (int off = 8; off; off >>= 1)
            part += __shfl_down_sync(0xffffffffu, part, off, 16);
        if (j0 == 0) hsh[kk] = part;
        __syncthreads();

        float T = Ts[i][tid];
        float dinv = 1.f / (tvd + eps);
        float zh = 0.f;
#pragma unroll
        for (int k2 = 0; k2 < NR; k2++)
            zh += g_Z[i * NC * NR + tid * NR + k2] * hsh[k2];
        Q[i][tid] = a1 * T - q3 * T * dinv + q3 * zh;
        __syncthreads();
    }

#pragma unroll 1
    for (int f = 0; f < NT; f++) {
        float acc = 0.f;
#pragma unroll
        for (int i = 0; i < NT; i++) acc += EIG.A[f * NT + i] * Q[i][tid];
        acc += 0.5f * (xv[f] + xv[NT + f]);
        out[(size_t)(b * NT + f) * NC + tid] = acc;
    }
}

// ---------------- K5: covariance, broadcast 8 batches -----------------------
__global__ void __launch_bounds__(256, 1) k_cov(float* __restrict__ out) {
    float* cov = out + MEAN_ELEMS;
    int patch = blockIdx.x;
    int fgBase = blockIdx.y * 16;
    int tid = threadIdx.x;

    __shared__ float Wsm[16 * 25];
    for (int idx = tid; idx < 16 * 25; idx += 256) Wsm[idx] = EIG.Wm[fgBase * 25 + idx];

    int c  = (patch >> 2) * 32 + (tid >> 3);
    int d0 = (patch & 3) * 32 + (tid & 7) * 4;

    float4 bt = *reinterpret_cast<const float4*>(&g_Bt[c * NC + d0]);
    float4 gg[NT];
#pragma unroll
    for (int i = 0; i < NT; i++)
        gg[i] = *reinterpret_cast<const float4*>(&g_G[(i * NC + c) * NC + d0]);
    __syncthreads();

#pragma unroll 1
    for (int t = 0; t < 16; t++) {
        int fg = fgBase + t;
        int f = fg / NT, g = fg % NT;
        const float* w = &Wsm[t * 25];
        float w24 = w[24];
        float4 acc;
        acc.x = w24 * bt.x; acc.y = w24 * bt.y; acc.z = w24 * bt.z; acc.w = w24 * bt.w;
#pragma unroll
        for (int i = 0; i < NT; i++) {
            float wi = w[i];
            acc.x += wi * gg[i].x;
            acc.y += wi * gg[i].y;
            acc.z += wi * gg[i].z;
            acc.w += wi * gg[i].w;
        }
        if (f == g && c >= d0 && c < d0 + 4)
            reinterpret_cast<float*>(&acc)[c - d0] += SIG2;
        size_t row = (size_t)(f * NC + c);
        size_t col = (size_t)(g * NC + d0);
        float* p = cov + row * COV_N + col;
#pragma unroll
        for (int b = 0; b < NB; b++) {
            __stcs(reinterpret_cast<float4*>(p), acc);
            p += COV_ELEMS;
        }
    }
}

// ---------------- launcher ---------------------------------------------------
extern "C" void kernel_launch(void* const* d_in, const int* in_sizes, int n_in,
                              void* d_out, int out_size) {
    const float* x  = (const float*)d_in[0];
    const float* V  = (const float*)d_in[1];
    const float* tv = (const float*)d_in[2];
    float* out = (float*)d_out;

    k_bt<<<64, 256>>>(V, tv);
    k_wood<<<24, 128>>>(V, tv);
    k_G<<<dim3(24, 4), 256>>>();
    k_mean<<<8, 128>>>(x, tv, out);
    k_cov<<<dim3(16, 36), 256>>>(out);
}

// round 17
// speedup vs baseline: 7.2026x; 1.3891x over previous
#include <cuda_runtime.h>
#include <cuda_bf16.h>
#include <math.h>

#define NB   8
#define NC   128
#define NL   48
#define NT   24
#define NR   8
#define SIG2 1.0001f
#define PICF ((float)(3.14159265358979323846 / 24.0))

#define COV_N      3072
#define COV_ELEMS  9437184ull
#define MEAN_ELEMS 24576

// ============================================================================
// Compile-time eigendecomposition of the CONSTANT matrix
// Kc[i][j] = exp(-pi/24*|i-j|), LAPACK ssyevd path (ssytd2 -> ssteqr('I') ->
// sort -> sormtr), with PER-OPERATION fp32 rounding emulated in constexpr
// double (r32 = round-to-float + FTZ). Reproduces the fp32 LAPACK trajectory
// to within ulps (validated passing in R16).
// ============================================================================

struct EigData {
    float U[NT * NT];
    float s[NT];
    float A[NT * NT];
    float Wm[NT * NT * 25];
};

__host__ __device__ constexpr double cfabsd(double x) { return x < 0.0 ? -x : x; }
__host__ __device__ constexpr double ccopysignd(double m, double s) {
    double a = m < 0.0 ? -m : m;
    return s >= 0.0 ? a : -a;
}

__host__ __device__ constexpr double r32(double x) {
    double ax = x < 0.0 ? -x : x;
    if (ax < 1.1754943508222875e-38) return 0.0;
    return (double)(float)x;
}
__host__ __device__ constexpr double rm(double a, double b) { return r32(a * b); }
__host__ __device__ constexpr double ra(double a, double b) { return r32(a + b); }
__host__ __device__ constexpr double rsb(double a, double b) { return r32(a - b); }
__host__ __device__ constexpr double rd(double a, double b) { return r32(a / b); }

__host__ __device__ constexpr double csq(double x) {
    if (x <= 0.0) return 0.0;
    double sc = 1.0, y = x;
    while (y >= 4.0)  { y *= 0.25; sc *= 2.0; }
    while (y < 0.25)  { y *= 4.0;  sc *= 0.5; }
    double g = 1.0;
    for (int i = 0; i < 8; i++) g = 0.5 * (g + y / g);
    return sc * g;
}
__host__ __device__ constexpr double rsq(double x) { return r32(csq(x)); }

__host__ __device__ constexpr double cexp_(double x) {
    const double LN2 = 0.69314718055994530941723212145818;
    double kd = x / LN2;
    int k = (int)(kd >= 0.0 ? kd + 0.5 : kd - 0.5);
    double r = x - (double)k * LN2;
    double t = 1.0, s = 1.0;
    for (int i = 1; i <= 15; i++) { t = t * r / (double)i; s += t; }
    double p = 1.0;
    int kk = k < 0 ? -k : k;
    for (int i = 0; i < kk; i++) p *= 2.0;
    return k < 0 ? s / p : s * p;
}

__host__ __device__ constexpr double c_lapy2(double x, double y) {
    double ax = cfabsd(x), ay = cfabsd(y);
    double w = ax > ay ? ax : ay;
    double z = ax > ay ? ay : ax;
    if (z == 0.0) return w;
    double q = rd(z, w);
    double arg = ra(1.0, rm(q, q));
    return rm(w, rsq(arg));
}

struct Rot { double c, s, r; };
__host__ __device__ constexpr Rot c_lartg(double f, double g) {
    Rot o{1.0, 0.0, f};
    if (g == 0.0) { o.c = 1.0; o.s = 0.0; o.r = f; }
    else if (f == 0.0) { o.c = 0.0; o.s = (g > 0.0 ? 1.0 : -1.0); o.r = cfabsd(g); }
    else {
        double t2 = ra(rm(f, f), rm(g, g));
        double d = rsq(t2);
        o.c = rd(cfabsd(f), d);
        o.r = ccopysignd(d, f);
        o.s = rd(g, o.r);
    }
    return o;
}

struct Ev2 { double rt1, rt2, cs1, sn1; };
__host__ __device__ constexpr Ev2 c_laev2(double a, double b, double c) {
    Ev2 o{0.0, 0.0, 1.0, 0.0};
    double sm = ra(a, c), df = rsb(a, c), adf = cfabsd(df);
    double tb = ra(b, b), ab = cfabsd(tb);
    double acmx = 0.0, acmn = 0.0;
    if (cfabsd(a) > cfabsd(c)) { acmx = a; acmn = c; } else { acmx = c; acmn = a; }
    double rt = 0.0;
    if (adf > ab)      { double q = rd(ab, adf); rt = rm(adf, rsq(ra(1.0, rm(q, q)))); }
    else if (adf < ab) { double q = rd(adf, ab); rt = rm(ab, rsq(ra(1.0, rm(q, q)))); }
    else               rt = rm(ab, rsq(2.0));
    int sgn1 = 1;
    if (sm < 0.0) {
        o.rt1 = rm(0.5, rsb(sm, rt)); sgn1 = -1;
        o.rt2 = rsb(rm(rd(acmx, o.rt1), acmn), rm(rd(b, o.rt1), b));
    } else if (sm > 0.0) {
        o.rt1 = rm(0.5, ra(sm, rt)); sgn1 = 1;
        o.rt2 = rsb(rm(rd(acmx, o.rt1), acmn), rm(rd(b, o.rt1), b));
    } else { o.rt1 = rm(0.5, rt); o.rt2 = rm(-0.5, rt); sgn1 = 1; }
    int sgn2 = 1; double cs = 0.0;
    if (df >= 0.0) { cs = ra(df, rt); sgn2 = 1; } else { cs = rsb(df, rt); sgn2 = -1; }
    double acs = cfabsd(cs);
    if (acs > ab) {
        double ct = rd(-tb, cs);
        o.sn1 = rd(1.0, rsq(ra(1.0, rm(ct, ct))));
        o.cs1 = rm(ct, o.sn1);
    } else {
        if (ab == 0.0) { o.cs1 = 1.0; o.sn1 = 0.0; }
        else {
            double tn = rd(-cs, tb);
            o.cs1 = rd(1.0, rsq(ra(1.0, rm(tn, tn))));
            o.sn1 = rm(tn, o.cs1);
        }
    }
    if (sgn1 == sgn2) { double tn = o.cs1; o.cs1 = -o.sn1; o.sn1 = tn; }
    return o;
}

__host__ __device__ constexpr EigData make_eig() {
    EigData E = {};
    const double TH = (double)PICF;
    double As[NT][NT] = {};
    double Zs[NT][NT] = {};
    double d[NT] = {}, e[NT] = {}, tau[NT] = {};

    for (int i = 0; i < NT; i++) {
        double ti = rm((double)i, TH);
        for (int j = 0; j < NT; j++) {
            double tj = rm((double)j, TH);
            As[i][j] = r32(cexp_(-cfabsd(rsb(ti, tj))));
            Zs[i][j] = (i == j) ? 1.0 : 0.0;
        }
    }

    // ---- SSYTD2 (lower), fp32-rounded per op ----
    for (int i = 0; i < NT - 1; i++) {
        double alpha = As[i + 1][i];
        double taui = 0.0;
        if (i < NT - 2) {
            double ss = 0.0;
            for (int r = i + 2; r < NT; r++) ss = ra(ss, rm(As[r][i], As[r][i]));
            if (ss != 0.0) {
                double xnorm = rsq(ss);
                double beta = -ccopysignd(c_lapy2(alpha, xnorm), alpha);
                taui = rd(rsb(beta, alpha), beta);
                double scal = rd(1.0, rsb(alpha, beta));
                for (int r = i + 2; r < NT; r++) As[r][i] = rm(As[r][i], scal);
                e[i] = beta;
                double xr_[NT] = {}, vr_[NT] = {}, wsh[NT] = {};
                for (int lane = i + 1; lane < NT; lane++) {
                    double vr = (lane == i + 1) ? 1.0 : As[lane][i];
                    double acc = 0.0;
                    for (int cc = i + 1; cc < NT; cc++) {
                        double vc = (cc == i + 1) ? 1.0 : As[cc][i];
                        acc = ra(acc, rm(As[lane][cc], vc));
                    }
                    xr_[lane] = rm(acc, taui);
                    vr_[lane] = vr;
                }
                double red[32] = {};
                for (int lane = i + 1; lane < NT; lane++) red[lane] = rm(vr_[lane], xr_[lane]);
                for (int o = 16; o; o >>= 1) {
                    double tmp[32] = {};
                    for (int j = 0; j < 32; j++) tmp[j] = ra(red[j], red[j ^ o]);
                    for (int j = 0; j < 32; j++) red[j] = tmp[j];
                }
                double pv = red[0];
                double a2 = rm(rm(-0.5, taui), pv);
                for (int lane = i + 1; lane < NT; lane++)
                    wsh[lane] = ra(xr_[lane], rm(a2, vr_[lane]));
                for (int lane = i + 1; lane < NT; lane++)
                    for (int cc = i + 1; cc < NT; cc++)
                        As[lane][cc] = rsb(As[lane][cc],
                                           ra(rm(vr_[lane], wsh[cc]), rm(wsh[lane], vr_[cc])));
            } else e[i] = alpha;
        } else e[i] = alpha;
        tau[i] = taui;
        d[i] = As[i][i];
    }
    d[NT - 1] = As[NT - 1][NT - 1];

    // ---- SSTEQR('I'), fp32-rounded per op ----
    const double eps = 5.9604645e-8, eps2 = 3.5527137e-15, safmin = 1.1754944e-38;
    int l1 = 0, jtot = 0;
    const int nmaxit = NT * 30;
    while (l1 < NT) {
        if (l1 > 0) e[l1 - 1] = 0.0;
        int m = l1;
        for (m = l1; m < NT - 1; m++) {
            double tst = cfabsd(e[m]);
            if (tst == 0.0) break;
            if (tst <= rm(rm(rsq(cfabsd(d[m])), rsq(cfabsd(d[m + 1]))), eps)) { e[m] = 0.0; break; }
        }
        int l = l1, lsv = l, lend = m, lendsv = lend;
        l1 = m + 1;
        if (lend == l) continue;
        if (cfabsd(d[lend]) < cfabsd(d[l])) { lend = lsv; l = lendsv; }

        if (lend > l) {
            for (;;) {
                if (l != lend) {
                    for (m = l; m < lend; m++) {
                        double tst = rm(e[m], e[m]);
                        if (tst <= ra(rm(rm(eps2, cfabsd(d[m])), cfabsd(d[m + 1])), safmin)) break;
                    }
                } else m = lend;
                if (m < lend) e[m] = 0.0;
                double p = d[l];
                if (m == l) { d[l] = p; l++; if (l <= lend) continue; else break; }
                if (m == l + 1) {
                    Ev2 v = c_laev2(d[l], e[l], d[l + 1]);
                    for (int lane = 0; lane < NT; lane++) {
                        double z1 = Zs[lane][l + 1], z0 = Zs[lane][l];
                        Zs[lane][l + 1] = rsb(rm(v.cs1, z1), rm(v.sn1, z0));
                        Zs[lane][l]     = ra(rm(v.sn1, z1), rm(v.cs1, z0));
                    }
                    d[l] = v.rt1; d[l + 1] = v.rt2; e[l] = 0.0;
                    l += 2; if (l <= lend) continue; else break;
                }
                if (jtot == nmaxit) break;
                jtot++;
                double g = rd(rsb(d[l + 1], p), rm(2.0, e[l]));
                double r = c_lapy2(g, 1.0);
                g = ra(rsb(d[m], p), rd(e[l], ra(g, ccopysignd(r, g))));
                double s = 1.0, c = 1.0;
                p = 0.0;
                double dn = d[m];
                for (int i2 = m - 1; i2 >= l; i2--) {
                    double ei = e[i2];
                    double f = rm(s, ei), b = rm(c, ei);
                    Rot ro = c_lartg(g, f);
                    c = ro.c; s = ro.s; r = ro.r;
                    if (i2 != m - 1) e[i2 + 1] = r;
                    g = rsb(dn, p);
                    double di = d[i2];
                    r = ra(rm(rsb(di, g), s), rm(rm(2.0, c), b));
                    p = rm(s, r);
                    d[i2 + 1] = ra(g, p);
                    g = rsb(rm(c, r), b);
                    dn = di;
                    for (int lane = 0; lane < NT; lane++) {
                        double z1 = Zs[lane][i2 + 1], z0 = Zs[lane][i2];
                        Zs[lane][i2 + 1] = ra(rm(c, z1), rm(s, z0));
                        Zs[lane][i2]     = rsb(rm(c, z0), rm(s, z1));
                    }
                }
                d[l] = rsb(dn, p);
                e[l] = g;
            }
        } else {
            for (;;) {
                if (l != lend) {
                    for (m = l; m > lend; m--) {
                        double tst = rm(e[m - 1], e[m - 1]);
                        if (tst <= ra(rm(rm(eps2, cfabsd(d[m])), cfabsd(d[m - 1])), safmin)) break;
                    }
                } else m = lend;
                if (m > lend) e[m - 1] = 0.0;
                double p = d[l];
                if (m == l) { d[l] = p; l--; if (l >= lend) continue; else break; }
                if (m == l - 1) {
                    Ev2 v = c_laev2(d[l - 1], e[l - 1], d[l]);
                    for (int lane = 0; lane < NT; lane++) {
                        double z1 = Zs[lane][l], z0 = Zs[lane][l - 1];
                        Zs[lane][l]     = rsb(rm(v.cs1, z1), rm(v.sn1, z0));
                        Zs[lane][l - 1] = ra(rm(v.sn1, z1), rm(v.cs1, z0));
                    }
                    d[l - 1] = v.rt1; d[l] = v.rt2; e[l - 1] = 0.0;
                    l -= 2; if (l >= lend) continue; else break;
                }
                if (jtot == nmaxit) break;
                jtot++;
                double g = rd(rsb(d[l - 1], p), rm(2.0, e[l - 1]));
                double r = c_lapy2(g, 1.0);
                g = ra(rsb(d[m], p), rd(e[l - 1], ra(g, ccopysignd(r, g))));
                double s = 1.0, c = 1.0;
                p = 0.0;
                double dc = d[m];
                for (int i2 = m; i2 <= l - 1; i2++) {
                    double ei = e[i2];
                    double f = rm(s, ei), b = rm(c, ei);
                    Rot ro = c_lartg(g, f);
                    c = ro.c; s = ro.s; r = ro.r;
                    if (i2 != m) e[i2 - 1] = r;
                    g = rsb(dc, p);
                    double dip = d[i2 + 1];
                    r = ra(rm(rsb(dip, g), s), rm(rm(2.0, c), b));
                    p = rm(s, r);
                    d[i2] = ra(g, p);
                    g = rsb(rm(c, r), b);
                    dc = dip;
                    for (int lane = 0; lane < NT; lane++) {
                        double z1 = Zs[lane][i2 + 1], z0 = Zs[lane][i2];
                        Zs[lane][i2 + 1] = rsb(rm(c, z1), rm(s, z0));
                        Zs[lane][i2]     = ra(rm(s, z1), rm(c, z0));
                    }
                }
                d[l] = rsb(dc, p);
                e[l - 1] = g;
            }
        }
    }

    for (int ii = 1; ii < NT; ii++) {
        int i = ii - 1, k = i;
        double p = d[i];
        for (int j = ii; j < NT; j++) if (d[j] < p) { k = j; p = d[j]; }
        if (k != i) {
            d[k] = d[i]; d[i] = p;
            for (int lane = 0; lane < NT; lane++) {
                double tm = Zs[lane][i]; Zs[lane][i] = Zs[lane][k]; Zs[lane][k] = tm;
            }
        }
    }

    for (int j = 0; j < NT; j++) {
        for (int i = NT - 2; i >= 0; i--) {
            double ti = tau[i];
            if (ti == 0.0) continue;
            double w = Zs[i + 1][j];
            for (int r = i + 2; r < NT; r++) w = ra(w, rm(As[r][i], Zs[r][j]));
            w = rm(w, ti);
            Zs[i + 1][j] = rsb(Zs[i + 1][j], w);
            for (int r = i + 2; r < NT; r++) Zs[r][j] = rsb(Zs[r][j], rm(As[r][i], w));
        }
    }

    for (int i = 0; i < NT; i++) E.s[i] = (float)d[i];
    for (int i = 0; i < NT; i++)
        for (int j = 0; j < NT; j++) E.U[i * NT + j] = (float)Zs[i][j];

    double kfc[NT][NT] = {};
    for (int f = 0; f < NT; f++) {
        double tf = rm((double)(NT + f), TH);
        for (int i2 = 0; i2 < NT; i2++) {
            double ti2 = rm((double)i2, TH);
            kfc[f][i2] = r32(cexp_(-cfabsd(rsb(tf, ti2))));
        }
    }
    double Aq[NT][NT] = {};
    for (int f = 0; f < NT; f++)
        for (int l2 = 0; l2 < NT; l2++) {
            double acc = 0.0;
            for (int i2 = 0; i2 < NT; i2++) acc = ra(acc, rm(kfc[f][i2], Zs[i2][l2]));
            Aq[f][l2] = acc;
            E.A[f * NT + l2] = (float)acc;
        }

    for (int fg = 0; fg < NT * NT; fg++) {
        int f = fg / NT, g2 = fg % NT;
        for (int i2 = 0; i2 < 25; i2++) {
            double v = 0.0;
            if (i2 == 24) {
                double tf = rm((double)(NT + f), TH), tg = rm((double)(NT + g2), TH);
                v = r32(cexp_(-cfabsd(rsb(tf, tg))));
            } else v = -rm(Aq[f][i2], Aq[g2][i2]);
            E.Wm[fg * 25 + i2] = (float)v;
        }
    }
    return E;
}

__device__ constexpr EigData EIG = make_eig();

// ============================================================================
// Runtime scratch + kernels
// ============================================================================
__device__ float g_Bt[NC * NC];
__device__ float g_W[NT * NC * NR];
__device__ float g_Z[NT * NC * NR];
__device__ float g_gamma[NT * NC];
__device__ float g_G[NT * NC * NC];

// ---------------- K0: Bt = V V^T + diag(task_var) ----------------
__global__ void k_bt(const float* __restrict__ V, const float* __restrict__ tv) {
    int idx = blockIdx.x * 256 + threadIdx.x;
    int c = idx >> 7, d = idx & 127;
    float acc = (c == d) ? tv[c] : 0.f;
#pragma unroll
    for (int k = 0; k < NR; k++) acc += V[c * NR + k] * V[d * NR + k];
    g_Bt[idx] = acc;
}

// ---------------- K2: low-rank factors per i -------------------------------
__global__ void k_wood(const float* __restrict__ Vg, const float* __restrict__ tv) {
    int i = blockIdx.x;       // 24 blocks
    int c = threadIdx.x;      // 128 threads
    __shared__ float Vs[NC][NR];
    __shared__ float Wsh[NC][NR];
    __shared__ float Ssm[NR][NR];
    __shared__ float Sinv[NR][NR];

    float si  = EIG.s[i];
    float eps = SIG2 / si;
    float dinv = 1.f / (tv[c] + eps);

    float w[NR];
#pragma unroll
    for (int k = 0; k < NR; k++) {
        float v = Vg[c * NR + k];
        Vs[c][k] = v;
        w[k] = v * dinv;
        Wsh[c][k] = w[k];
    }
    __syncthreads();

    if (c < NR * NR) {
        int k = c >> 3, l = c & 7;
        float acc = 0.f;
        for (int e = 0; e < NC; e++) acc += Vs[e][k] * Wsh[e][l];
        Ssm[k][l] = ((k == l) ? 1.f : 0.f) + acc;
    }
    __syncthreads();
    if (c == 0) {
        float M[NR][2 * NR];
        for (int r = 0; r < NR; r++)
            for (int c2 = 0; c2 < NR; c2++) {
                M[r][c2] = Ssm[r][c2];
                M[r][NR + c2] = (r == c2) ? 1.f : 0.f;
            }
        for (int p = 0; p < NR; p++) {
            float piv = 1.f / M[p][p];
            for (int c2 = 0; c2 < 2 * NR; c2++) M[p][c2] *= piv;
            for (int r = 0; r < NR; r++) {
                if (r == p) continue;
                float fct = M[r][p];
                for (int c2 = 0; c2 < 2 * NR; c2++) M[r][c2] -= fct * M[p][c2];
            }
        }
        for (int r = 0; r < NR; r++)
            for (int c2 = 0; c2 < NR; c2++) Sinv[r][c2] = M[r][NR + c2];
    }
    __syncthreads();

    float z[NR];
#pragma unroll
    for (int k = 0; k < NR; k++) {
        float acc = 0.f;
#pragma unroll
        for (int l = 0; l < NR; l++) acc += w[l] * Sinv[l][k];
        z[k] = acc;
    }
    int base = i * NC * NR + c * NR;
#pragma unroll
    for (int k = 0; k < NR; k++) { g_W[base + k] = w[k]; g_Z[base + k] = z[k]; }
    g_gamma[i * NC + c] = (-eps + eps * eps * dinv) / si;
}

// ---------------- K3: G_i = alpha*Bt + gamma*I - beta * Z W^T ---------------
__global__ void k_G() {
    int i = blockIdx.x;
    int cb = blockIdx.y;
    int tid = threadIdx.x;  // 256
    __shared__ float Wsh[NC][NR + 1];
    __shared__ float gam[NC];
    for (int idx = tid; idx < NC * NR; idx += 256)
        Wsh[idx >> 3][idx & 7] = g_W[i * NC * NR + idx];
    for (int idx = tid; idx < NC; idx += 256) gam[idx] = g_gamma[i * NC + idx];
    __syncthreads();

    float si = EIG.s[i];
    float eps = SIG2 / si;
    float alpha = 1.f / si;
    float beta = eps * eps / si;

    int c  = cb * 32 + (tid >> 3);
    int dg = (tid & 7) * 16;
    float z[NR];
#pragma unroll
    for (int k = 0; k < NR; k++) z[k] = g_Z[i * NC * NR + c * NR + k];

    const float4* btp = reinterpret_cast<const float4*>(&g_Bt[c * NC + dg]);
    float4* gout = reinterpret_cast<float4*>(&g_G[(i * NC + c) * NC + dg]);
#pragma unroll
    for (int v = 0; v < 4; v++) {
        float4 b = btp[v];
        float o[4];
#pragma unroll
        for (int e = 0; e < 4; e++) {
            int d = dg + v * 4 + e;
            float dot = 0.f;
#pragma unroll
            for (int k = 0; k < NR; k++) dot += z[k] * Wsh[d][k];
            float val = alpha * ((const float*)&b)[e] - beta * dot;
            if (d == c) val += gam[c];
            o[e] = val;
        }
        gout[v] = make_float4(o[0], o[1], o[2], o[3]);
    }
}

// ---------------- K4: mean, warp-parallel (24 warps = 24 eigen-indices) -----
// grid 8 (batch), 768 threads. All-coalesced loads; single barrier chain.
__global__ void __launch_bounds__(768, 1) k_mean(
    const float* __restrict__ x, const float* __restrict__ tv,
    float* __restrict__ out) {
    int b = blockIdx.x, tid = threadIdx.x;
    __shared__ float Ys[NT][NC];     // Y[j][c]
    __shared__ float locs[NT][NC];   // loc_phase[f][c]
    __shared__ float Ts[NT][NC];     // T[i][c]
    __shared__ float Q[NT][NC];      // Q[i][d]
    __shared__ float Us[NT][NT];
    __shared__ float tvs[NC];

    const float* xb = x + (size_t)b * NC * NL;

    // Phase 1: coalesced Y/loc construction (idx = c*24 + j -> contiguous j)
    for (int idx = tid; idx < NT * NT; idx += 768) Us[idx / NT][idx % NT] = EIG.U[idx];
    if (tid < NC) tvs[tid] = tv[tid];
    for (int idx = tid; idx < NC * NT; idx += 768) {
        int c = idx / NT, j = idx % NT;
        const float* xr = xb + (size_t)c * NL;
        float a0 = xr[j], a1v = xr[NT + j];
        int h = j >> 1;
        float m = 0.5f * (xr[12 + h] + xr[36 + h]);
        Ys[j][c]   = a1v - m;
        locs[j][c] = 0.5f * (a0 + a1v);
    }
    __syncthreads();

    // Phase 2: T[i][c] = sum_j U[i][j] Y[j][c]
    for (int idx = tid; idx < NT * NC; idx += 768) {
        int i = idx >> 7, c = idx & 127;
        float acc = 0.f;
#pragma unroll
        for (int j = 0; j < NT; j++) acc += Us[i][j] * Ys[j][c];
        Ts[i][c] = acc;
    }
    __syncthreads();

    // Phase 3: warp i computes h[k] then Q[i][d]
    {
        int i = tid >> 5;        // 0..23
        int lane = tid & 31;
        float si = EIG.s[i];
        float eps = SIG2 / si;
        float a1 = 1.f / si;
        float q3 = eps / si;

        float hk[NR];
#pragma unroll
        for (int k = 0; k < NR; k++) hk[k] = 0.f;
#pragma unroll
        for (int t = 0; t < 4; t++) {
            int c = lane + 32 * t;
            const float4* wp = reinterpret_cast<const float4*>(&g_W[(i * NC + c) * NR]);
            float4 w0 = wp[0], w1 = wp[1];
            float T = Ts[i][c];
            hk[0] += w0.x * T; hk[1] += w0.y * T; hk[2] += w0.z * T; hk[3] += w0.w * T;
            hk[4] += w1.x * T; hk[5] += w1.y * T; hk[6] += w1.z * T; hk[7] += w1.w * T;
        }
#pragma unroll
        for (int off = 16; off; off >>= 1) {
#pragma unroll
            for (int k = 0; k < NR; k++)
                hk[k] += __shfl_xor_sync(0xffffffffu, hk[k], off);
        }

#pragma unroll
        for (int t = 0; t < 4; t++) {
            int d = lane + 32 * t;
            const float4* zp = reinterpret_cast<const float4*>(&g_Z[(i * NC + d) * NR]);
            float4 z0 = zp[0], z1 = zp[1];
            float zh = z0.x * hk[0] + z0.y * hk[1] + z0.z * hk[2] + z0.w * hk[3]
                     + z1.x * hk[4] + z1.y * hk[5] + z1.z * hk[6] + z1.w * hk[7];
            float T = Ts[i][d];
            float dinv = 1.f / (tvs[d] + eps);
            Q[i][d] = a1 * T - q3 * T * dinv + q3 * zh;
        }
    }
    __syncthreads();

    // Phase 4: mean[b,f,d] = sum_i A[f][i] Q[i][d] + locs[f][d]
    for (int idx = tid; idx < NT * NC; idx += 768) {
        int f = idx >> 7, dv = idx & 127;
        float acc = 0.f;
#pragma unroll
        for (int i = 0; i < NT; i++) acc += EIG.A[f * NT + i] * Q[i][dv];
        out[(size_t)(b * NT + f) * NC + dv] = acc + locs[f][dv];
    }
}

// ---------------- K5: covariance, broadcast 8 batches -----------------------
__global__ void __launch_bounds__(256, 1) k_cov(float* __restrict__ out) {
    float* cov = out + MEAN_ELEMS;
    int patch = blockIdx.x;
    int fgBase = blockIdx.y * 16;
    int tid = threadIdx.x;

    __shared__ float Wsm[16 * 25];
    for (int idx = tid; idx < 16 * 25; idx += 256) Wsm[idx] = EIG.Wm[fgBase * 25 + idx];

    int c  = (patch >> 2) * 32 + (tid >> 3);
    int d0 = (patch & 3) * 32 + (tid & 7) * 4;

    float4 bt = *reinterpret_cast<const float4*>(&g_Bt[c * NC + d0]);
    float4 gg[NT];
#pragma unroll
    for (int i = 0; i < NT; i++)
        gg[i] = *reinterpret_cast<const float4*>(&g_G[(i * NC + c) * NC + d0]);
    __syncthreads();

#pragma unroll 1
    for (int t = 0; t < 16; t++) {
        int fg = fgBase + t;
        int f = fg / NT, g = fg % NT;
        const float* w = &Wsm[t * 25];
        float w24 = w[24];
        float4 acc;
        acc.x = w24 * bt.x; acc.y = w24 * bt.y; acc.z = w24 * bt.z; acc.w = w24 * bt.w;
#pragma unroll
        for (int i = 0; i < NT; i++) {
            float wi = w[i];
            acc.x += wi * gg[i].x;
            acc.y += wi * gg[i].y;
            acc.z += wi * gg[i].z;
            acc.w += wi * gg[i].w;
        }
        if (f == g && c >= d0 && c < d0 + 4)
            reinterpret_cast<float*>(&acc)[c - d0] += SIG2;
        size_t row = (size_t)(f * NC + c);
        size_t col = (size_t)(g * NC + d0);
        float* p = cov + row * COV_N + col;
#pragma unroll
        for (int b = 0; b < NB; b++) {
            __stcs(reinterpret_cast<float4*>(p), acc);
            p += COV_ELEMS;
        }
    }
}

// ---------------- launcher ---------------------------------------------------
extern "C" void kernel_launch(void* const* d_in, const int* in_sizes, int n_in,
                              void* d_out, int out_size) {
    const float* x  = (const float*)d_in[0];
    const float* V  = (const float*)d_in[1];
    const float* tv = (const float*)d_in[2];
    float* out = (float*)d_out;

    k_bt<<<64, 256>>>(V, tv);
    k_wood<<<24, 128>>>(V, tv);
    k_G<<<dim3(24, 4), 256>>>();
    k_mean<<<8, 768>>>(x, tv, out);
    k_cov<<<dim3(16, 36), 256>>>(out);
}